// round 2
// baseline (speedup 1.0000x reference)
#include <cuda_runtime.h>
#include <cuda_bf16.h>
#include <math.h>

// Problem constants
#define B_SZ   2
#define S_LEN  4096
#define HID    2048
#define Q_LR   768
#define KV_LR  512
#define QK_ROPE 64
#define QK_NOPE 128
#define HEADS  16
#define QK_HEAD 192          // 128 + 64
#define KV_HEAD 256          // 128 + 128
#define NTOK   (B_SZ * S_LEN)   // 8192
#define OUT_D  512

// Scratch (device globals: allocation-free per harness rules)
__device__ float g_qc [NTOK * Q_LR];          // q_c (pre-LN)
__device__ float g_qln[NTOK * Q_LR];          // q_c after LN
__device__ float g_kvc[NTOK * (KV_LR + QK_ROPE)]; // kv_c (pre-LN, incl k_rope)
__device__ float g_kvln[NTOK * KV_LR];        // kv_lr after LN
__device__ float g_cos[S_LEN * 32];
__device__ float g_sin[S_LEN * 32];

// ---------------------------------------------------------------------------
// RoPE cos/sin table (computed in double for accuracy)
// ---------------------------------------------------------------------------
__global__ void rope_table_kernel(float* __restrict__ ct, float* __restrict__ st) {
    int idx = blockIdx.x * blockDim.x + threadIdx.x;
    if (idx >= S_LEN * 32) return;
    int s = idx >> 5;
    int f = idx & 31;
    double inv = exp(-(double)f * (log(10000.0) / 32.0));
    double fr = (double)s * inv;
    ct[idx] = (float)cos(fr);
    st[idx] = (float)sin(fr);
}

// ---------------------------------------------------------------------------
// GEMM (NT): C[m,n] = sum_k A[m,k] * B[n,k] + bias[n]
// A: [M,K] row-major, B: [N,K] row-major. 128x128x16 tiles, 256 threads, 8x8.
// EPI 0: plain write to out [M,N] (with N guard)
// EPI 1: q up-proj -> RoPE on rope cols (shfl partner) -> scatter to out layout
// EPI 2: kv up-proj -> k_nope / v scatter to out layout
// ---------------------------------------------------------------------------
template <int EPI>
__global__ __launch_bounds__(256)
void gemm_nt(const float* __restrict__ A, const float* __restrict__ Bm,
             const float* __restrict__ bias, float* __restrict__ out,
             int M, int N, int K,
             const float* __restrict__ ctab, const float* __restrict__ stab)
{
    __shared__ float As[16][132];
    __shared__ float Bs[16][132];

    const int tid = threadIdx.x;
    const int m0 = blockIdx.y * 128;
    const int n0 = blockIdx.x * 128;
    const int tx = tid & 15;
    const int ty = tid >> 4;

    float acc[8][8];
#pragma unroll
    for (int i = 0; i < 8; i++)
#pragma unroll
        for (int j = 0; j < 8; j++) acc[i][j] = 0.f;

    for (int k0 = 0; k0 < K; k0 += 16) {
#pragma unroll
        for (int l = 0; l < 2; l++) {
            int f = tid + l * 256;       // 0..511
            int row = f >> 2;            // 0..127
            int kq = f & 3;              // float4 index within 16
            float4 va = *(const float4*)(A + (size_t)(m0 + row) * K + (k0 + kq * 4));
            As[kq * 4 + 0][row] = va.x;
            As[kq * 4 + 1][row] = va.y;
            As[kq * 4 + 2][row] = va.z;
            As[kq * 4 + 3][row] = va.w;
            float4 vb = make_float4(0.f, 0.f, 0.f, 0.f);
            if (n0 + row < N)
                vb = *(const float4*)(Bm + (size_t)(n0 + row) * K + (k0 + kq * 4));
            Bs[kq * 4 + 0][row] = vb.x;
            Bs[kq * 4 + 1][row] = vb.y;
            Bs[kq * 4 + 2][row] = vb.z;
            Bs[kq * 4 + 3][row] = vb.w;
        }
        __syncthreads();
#pragma unroll
        for (int k = 0; k < 16; k++) {
            float a[8], b[8];
            *(float4*)(a)     = *(const float4*)(&As[k][ty * 8]);
            *(float4*)(a + 4) = *(const float4*)(&As[k][ty * 8 + 4]);
            *(float4*)(b)     = *(const float4*)(&Bs[k][tx * 8]);
            *(float4*)(b + 4) = *(const float4*)(&Bs[k][tx * 8 + 4]);
#pragma unroll
            for (int i = 0; i < 8; i++)
#pragma unroll
                for (int j = 0; j < 8; j++)
                    acc[i][j] = fmaf(a[i], b[j], acc[i][j]);
        }
        __syncthreads();
    }

    // bias per column
    float bv[8];
#pragma unroll
    for (int j = 0; j < 8; j++) {
        int n = n0 + tx * 8 + j;
        bv[j] = (n < N) ? bias[n] : 0.f;
    }

    if (EPI == 0) {
#pragma unroll
        for (int i = 0; i < 8; i++) {
            int m = m0 + ty * 8 + i;
#pragma unroll
            for (int j = 0; j < 8; j++) {
                int n = n0 + tx * 8 + j;
                if (n < N) out[(size_t)m * N + n] = acc[i][j] + bv[j];
            }
        }
    } else if (EPI == 1) {
        // q: N = H*192. cols [h*192, h*192+128) = q_nope, [h*192+128, +192) = rope
#pragma unroll
        for (int i = 0; i < 8; i++) {
            int m = m0 + ty * 8 + i;
            int s = m & (S_LEN - 1);
            int bb = m >> 12;
#pragma unroll
            for (int j = 0; j < 8; j++) {
                int n = n0 + tx * 8 + j;
                float val = acc[i][j] + bv[j];
                // rope partner lives at column n^32 == thread tx^4, same j,i
                float partner = __shfl_xor_sync(0xffffffffu, val, 4);
                int h = n / QK_HEAD;
                int d = n - h * QK_HEAD;
                float res = val;
                if (d >= QK_NOPE) {
                    int r = d - QK_NOPE;        // 0..63
                    int fidx = r & 31;
                    float c = ctab[s * 32 + fidx];
                    float sn = stab[s * 32 + fidx];
                    res = val * c + ((r < 32) ? -partner : partner) * sn;
                }
                out[(((size_t)bb * HEADS + h) * S_LEN + s) * OUT_D + d] = res;
            }
        }
    } else {
        // kv: N = H*256. d<128 -> k_nope at off 192+d ; d>=128 -> v at off 256+d
#pragma unroll
        for (int i = 0; i < 8; i++) {
            int m = m0 + ty * 8 + i;
            int s = m & (S_LEN - 1);
            int bb = m >> 12;
#pragma unroll
            for (int j = 0; j < 8; j++) {
                int n = n0 + tx * 8 + j;
                int h = n >> 8;
                int d = n & 255;
                int off = (d < 128) ? (192 + d) : (256 + d);
                out[(((size_t)bb * HEADS + h) * S_LEN + s) * OUT_D + off] = acc[i][j] + bv[j];
            }
        }
    }
}

// ---------------------------------------------------------------------------
// Row LayerNorm (two-pass, matches reference numerics)
// in: [NTOK, ld], normalize first ncols cols, out: [NTOK, ncols]
// ---------------------------------------------------------------------------
__global__ __launch_bounds__(256)
void ln_kernel(const float* __restrict__ in, int ld, int ncols,
               const float* __restrict__ gamma, const float* __restrict__ beta,
               float* __restrict__ out)
{
    __shared__ float row[768];
    __shared__ float red[256];
    int r = blockIdx.x;
    const float* src = in + (size_t)r * ld;

    float lsum = 0.f;
    for (int c = threadIdx.x; c < ncols; c += 256) {
        float v = src[c];
        row[c] = v;
        lsum += v;
    }
    red[threadIdx.x] = lsum;
    __syncthreads();
    for (int s = 128; s > 0; s >>= 1) {
        if (threadIdx.x < s) red[threadIdx.x] += red[threadIdx.x + s];
        __syncthreads();
    }
    float mu = red[0] / (float)ncols;
    __syncthreads();

    float lsq = 0.f;
    for (int c = threadIdx.x; c < ncols; c += 256) {
        float d = row[c] - mu;
        lsq += d * d;
    }
    red[threadIdx.x] = lsq;
    __syncthreads();
    for (int s = 128; s > 0; s >>= 1) {
        if (threadIdx.x < s) red[threadIdx.x] += red[threadIdx.x + s];
        __syncthreads();
    }
    float var = red[0] / (float)ncols;
    float inv = rsqrtf(var + 1e-5f);

    for (int c = threadIdx.x; c < ncols; c += 256)
        out[(size_t)r * ncols + c] = (row[c] - mu) * inv * gamma[c] + beta[c];
}

// ---------------------------------------------------------------------------
// k_rot: RoPE on kv_c[:, 512:576] (NOT layernormed), broadcast to all heads
// ---------------------------------------------------------------------------
__global__ void krot_kernel(const float* __restrict__ kvc,
                            const float* __restrict__ ctab,
                            const float* __restrict__ stab,
                            float* __restrict__ out)
{
    int t = blockIdx.x;              // token 0..8191
    int d = threadIdx.x;             // 0..63
    int s = t & (S_LEN - 1);
    int bb = t >> 12;
    const float* kr = kvc + (size_t)t * (KV_LR + QK_ROPE) + KV_LR;
    float x = kr[d];
    float p = kr[d ^ 32];
    int fidx = d & 31;
    float c = ctab[s * 32 + fidx];
    float sn = stab[s * 32 + fidx];
    float res = x * c + ((d < 32) ? -p : p) * sn;
#pragma unroll
    for (int h = 0; h < HEADS; h++)
        out[(((size_t)bb * HEADS + h) * S_LEN + s) * OUT_D + 320 + d] = res;
}

// ---------------------------------------------------------------------------
extern "C" void kernel_launch(void* const* d_in, const int* in_sizes, int n_in,
                              void* d_out, int out_size)
{
    const float* hidden  = (const float*)d_in[0];
    const float* w_qa    = (const float*)d_in[1];
    const float* b_qa    = (const float*)d_in[2];
    const float* g_qa_ln = (const float*)d_in[3];
    const float* b_qa_ln = (const float*)d_in[4];
    const float* w_qb    = (const float*)d_in[5];
    const float* b_qb    = (const float*)d_in[6];
    const float* w_kva   = (const float*)d_in[7];
    const float* b_kva   = (const float*)d_in[8];
    const float* g_kva_ln= (const float*)d_in[9];
    const float* b_kva_ln= (const float*)d_in[10];
    const float* w_kvb   = (const float*)d_in[11];
    const float* b_kvb   = (const float*)d_in[12];
    float* out = (float*)d_out;

    float *qc, *qln, *kvc, *kvln, *ct, *st;
    cudaGetSymbolAddress((void**)&qc,  g_qc);
    cudaGetSymbolAddress((void**)&qln, g_qln);
    cudaGetSymbolAddress((void**)&kvc, g_kvc);
    cudaGetSymbolAddress((void**)&kvln,g_kvln);
    cudaGetSymbolAddress((void**)&ct,  g_cos);
    cudaGetSymbolAddress((void**)&st,  g_sin);

    rope_table_kernel<<<(S_LEN * 32 + 255) / 256, 256>>>(ct, st);

    // Stage A: down-projections (write pre-LN scratch)
    gemm_nt<0><<<dim3(6, 64), 256>>>(hidden, w_qa, b_qa, qc,
                                     NTOK, Q_LR, HID, nullptr, nullptr);
    gemm_nt<0><<<dim3(5, 64), 256>>>(hidden, w_kva, b_kva, kvc,
                                     NTOK, KV_LR + QK_ROPE, HID, nullptr, nullptr);

    // LayerNorms
    ln_kernel<<<NTOK, 256>>>(qc,  Q_LR,            Q_LR,  g_qa_ln,  b_qa_ln,  qln);
    ln_kernel<<<NTOK, 256>>>(kvc, KV_LR + QK_ROPE, KV_LR, g_kva_ln, b_kva_ln, kvln);

    // Stage B: q up-projection + RoPE + scatter
    gemm_nt<1><<<dim3(24, 64), 256>>>(qln, w_qb, b_qb, out,
                                      NTOK, HEADS * QK_HEAD, Q_LR, ct, st);
    // Stage C: kv up-projection + scatter
    gemm_nt<2><<<dim3(32, 64), 256>>>(kvln, w_kvb, b_kvb, out,
                                      NTOK, HEADS * KV_HEAD, KV_LR, ct, st);

    // k_rot broadcast
    krot_kernel<<<NTOK, 64>>>(kvc, ct, st, out);
}

// round 3
// speedup vs baseline: 1.3857x; 1.3857x over previous
#include <cuda_runtime.h>
#include <cuda_bf16.h>
#include <math.h>

// Problem constants
#define B_SZ   2
#define S_LEN  4096
#define HID    2048
#define Q_LR   768
#define KV_LR  512
#define QK_ROPE 64
#define QK_NOPE 128
#define HEADS  16
#define QK_HEAD 192          // 128 + 64
#define KV_HEAD 256          // 128 + 128
#define NTOK   (B_SZ * S_LEN)   // 8192
#define OUT_D  512

// Scratch (device globals: allocation-free per harness rules)
__device__ float g_qc [NTOK * Q_LR];
__device__ float g_qln[NTOK * Q_LR];
__device__ float g_kvc[NTOK * (KV_LR + QK_ROPE)];
__device__ float g_kvln[NTOK * KV_LR];
__device__ float g_cos[S_LEN * 32];
__device__ float g_sin[S_LEN * 32];

// ---------------------------------------------------------------------------
// RoPE cos/sin table (double precision for accuracy)
// ---------------------------------------------------------------------------
__global__ void rope_table_kernel(float* __restrict__ ct, float* __restrict__ st) {
    int idx = blockIdx.x * blockDim.x + threadIdx.x;
    if (idx >= S_LEN * 32) return;
    int s = idx >> 5;
    int f = idx & 31;
    double inv = exp(-(double)f * (log(10000.0) / 32.0));
    double fr = (double)s * inv;
    ct[idx] = (float)cos(fr);
    st[idx] = (float)sin(fr);
}

// ---------------------------------------------------------------------------
// TF32 helpers
// ---------------------------------------------------------------------------
__device__ __forceinline__ unsigned f2tf32(float x) {
    unsigned r;
    asm("cvt.rna.tf32.f32 %0, %1;" : "=r"(r) : "f"(x));
    return r;
}
__device__ __forceinline__ void split_tf32(float v, unsigned& hi, unsigned& lo) {
    hi = f2tf32(v);
    float rem = v - __uint_as_float(hi);
    lo = f2tf32(rem);
}
__device__ __forceinline__ void mma8(float* d, const unsigned* a, const unsigned* b) {
    asm volatile(
        "mma.sync.aligned.m16n8k8.row.col.f32.tf32.tf32.f32 "
        "{%0,%1,%2,%3},{%4,%5,%6,%7},{%8,%9},{%0,%1,%2,%3};"
        : "+f"(d[0]), "+f"(d[1]), "+f"(d[2]), "+f"(d[3])
        : "r"(a[0]), "r"(a[1]), "r"(a[2]), "r"(a[3]), "r"(b[0]), "r"(b[1]));
}
__device__ __forceinline__ void cp16(float* s, const float* g, bool pred) {
    unsigned sa = (unsigned)__cvta_generic_to_shared(s);
    int sz = pred ? 16 : 0;
    asm volatile("cp.async.cg.shared.global [%0], [%1], 16, %2;"
                 :: "r"(sa), "l"(g), "r"(sz));
}
__device__ __forceinline__ void cp_commit() { asm volatile("cp.async.commit_group;"); }
__device__ __forceinline__ void cp_wait0()  { asm volatile("cp.async.wait_group 0;"); }

// ---------------------------------------------------------------------------
// TF32 tensor-core GEMM (NT): C[m,n] = sum_k A[m,k]*Bm[n,k] + bias[n]
// CTA tile 128x128, kblock 32, 8 warps (4x2), warp tile 32x64, 3xTF32.
// EPI 0: plain store [M,N] (N guard)
// EPI 1: q up-proj + in-register RoPE (partner = nt^4, same thread) + scatter
// EPI 2: kv up-proj + k_nope/v scatter
// ---------------------------------------------------------------------------
#define TS 36                 // padded k-stride (floats): conflict-free frags
#define BUF (128 * TS)        // one tile buffer
#define SMEM_BYTES (4 * BUF * (int)sizeof(float))   // A[2]+B[2] = 73728

template <int EPI>
__global__ __launch_bounds__(256)
void gemm_mma(const float* __restrict__ A, const float* __restrict__ Bm,
              const float* __restrict__ bias, float* __restrict__ out,
              int M, int N, int K,
              const float* __restrict__ ctab, const float* __restrict__ stab)
{
    extern __shared__ float smem[];
    float* As = smem;              // [2][128][TS]
    float* Bs = smem + 2 * BUF;    // [2][128][TS]

    const int tid  = threadIdx.x;
    const int lane = tid & 31;
    const int warp = tid >> 5;
    const int wm = warp & 3;       // 0..3 along M (32 rows each)
    const int wn = warp >> 2;      // 0..1 along N (64 cols each)
    const int m0 = blockIdx.y * 128;
    const int n0 = blockIdx.x * 128;
    const int r = lane >> 2;       // 0..7
    const int c = lane & 3;        // 0..3

    const int lrow = tid >> 3;     // 0..31 base? (f>>3 with f=tid+l*256)
    const int lq   = tid & 7;

    float acc[2][8][4];
#pragma unroll
    for (int mt = 0; mt < 2; mt++)
#pragma unroll
        for (int nt = 0; nt < 8; nt++)
#pragma unroll
            for (int e = 0; e < 4; e++) acc[mt][nt][e] = 0.f;

    const int KB = K >> 5;   // kblocks of 32

    // prefetch tile 0
    {
        const int k0 = 0;
#pragma unroll
        for (int l = 0; l < 4; l++) {
            int row = lrow + l * 32;
            cp16(&As[row * TS + lq * 4], A + (size_t)(m0 + row) * K + k0 + lq * 4, true);
            bool ok = (n0 + row) < N;
            const float* gb = Bm + (size_t)(ok ? (n0 + row) : 0) * K + k0 + lq * 4;
            cp16(&Bs[row * TS + lq * 4], gb, ok);
        }
        cp_commit();
    }

    for (int kb = 0; kb < KB; kb++) {
        cp_wait0();
        __syncthreads();
        const int cur = kb & 1;
        if (kb + 1 < KB) {
            const int nxt = cur ^ 1;
            const int k0 = (kb + 1) << 5;
#pragma unroll
            for (int l = 0; l < 4; l++) {
                int row = lrow + l * 32;
                cp16(&As[nxt * BUF + row * TS + lq * 4],
                     A + (size_t)(m0 + row) * K + k0 + lq * 4, true);
                bool ok = (n0 + row) < N;
                const float* gb = Bm + (size_t)(ok ? (n0 + row) : 0) * K + k0 + lq * 4;
                cp16(&Bs[nxt * BUF + row * TS + lq * 4], gb, ok);
            }
            cp_commit();
        }

        const float* a_base = As + cur * BUF;
        const float* b_base = Bs + cur * BUF;
#pragma unroll
        for (int kk = 0; kk < 32; kk += 8) {
            unsigned ah[2][4], al[2][4], bh[8][2], bl[8][2];
#pragma unroll
            for (int mt = 0; mt < 2; mt++) {
                int mr = wm * 32 + mt * 16 + r;
                float v0 = a_base[mr * TS + kk + c];
                float v1 = a_base[(mr + 8) * TS + kk + c];
                float v2 = a_base[mr * TS + kk + c + 4];
                float v3 = a_base[(mr + 8) * TS + kk + c + 4];
                split_tf32(v0, ah[mt][0], al[mt][0]);
                split_tf32(v1, ah[mt][1], al[mt][1]);
                split_tf32(v2, ah[mt][2], al[mt][2]);
                split_tf32(v3, ah[mt][3], al[mt][3]);
            }
#pragma unroll
            for (int nt = 0; nt < 8; nt++) {
                int nr = wn * 64 + nt * 8 + r;
                float w0 = b_base[nr * TS + kk + c];
                float w1 = b_base[nr * TS + kk + c + 4];
                split_tf32(w0, bh[nt][0], bl[nt][0]);
                split_tf32(w1, bh[nt][1], bl[nt][1]);
            }
#pragma unroll
            for (int mt = 0; mt < 2; mt++)
#pragma unroll
                for (int nt = 0; nt < 8; nt++) {
                    mma8(acc[mt][nt], ah[mt], bh[nt]);
                    mma8(acc[mt][nt], ah[mt], bl[nt]);
                    mma8(acc[mt][nt], al[mt], bh[nt]);
                }
        }
        __syncthreads();
    }

    // ---- add bias into accumulators ----
#pragma unroll
    for (int nt = 0; nt < 8; nt++) {
        int nb = n0 + wn * 64 + nt * 8 + 2 * c;
        float b0, b1;
        if (EPI == 0) {
            b0 = (nb < N) ? bias[nb] : 0.f;
            b1 = (nb + 1 < N) ? bias[nb + 1] : 0.f;
        } else {
            b0 = bias[nb];
            b1 = bias[nb + 1];
        }
#pragma unroll
        for (int mt = 0; mt < 2; mt++) {
            acc[mt][nt][0] += b0;
            acc[mt][nt][1] += b1;
            acc[mt][nt][2] += b0;
            acc[mt][nt][3] += b1;
        }
    }

    // ---- epilogue ----
    if (EPI == 0) {
#pragma unroll
        for (int mt = 0; mt < 2; mt++)
#pragma unroll
            for (int half = 0; half < 2; half++) {
                int m = m0 + wm * 32 + mt * 16 + r + half * 8;
#pragma unroll
                for (int nt = 0; nt < 8; nt++) {
                    int n = n0 + wn * 64 + nt * 8 + 2 * c;
                    if (n < N)
                        *(float2*)(out + (size_t)m * N + n) =
                            make_float2(acc[mt][nt][half * 2], acc[mt][nt][half * 2 + 1]);
                }
            }
    } else if (EPI == 1) {
#pragma unroll
        for (int mt = 0; mt < 2; mt++)
#pragma unroll
            for (int half = 0; half < 2; half++) {
                int m = m0 + wm * 32 + mt * 16 + r + half * 8;
                int s = m & (S_LEN - 1);
                int bb = m >> 12;
#pragma unroll
                for (int nt = 0; nt < 8; nt++) {
                    int n_base = n0 + wn * 64 + nt * 8;
                    int h = ((n_base >> 6) * 43) >> 7;           // n_base / 192
                    int d0 = n_base - h * 192 + 2 * c;
                    size_t obase = (((size_t)(bb * HEADS + h)) * S_LEN + s) * OUT_D;
                    float v0 = acc[mt][nt][half * 2];
                    float v1 = acc[mt][nt][half * 2 + 1];
                    if (d0 >= 128) {
                        int fi = d0 & 31;                        // 128 ≡ 0 mod 32
                        float c0 = ctab[s * 32 + fi],     s0 = stab[s * 32 + fi];
                        float c1 = ctab[s * 32 + fi + 1], s1 = stab[s * 32 + fi + 1];
                        float p0 = acc[mt][nt ^ 4][half * 2];
                        float p1 = acc[mt][nt ^ 4][half * 2 + 1];
                        float sg = (d0 & 32) ? 1.f : -1.f;       // r<32 -> -partner
                        v0 = v0 * c0 + sg * p0 * s0;
                        v1 = v1 * c1 + sg * p1 * s1;
                    }
                    *(float2*)(out + obase + d0) = make_float2(v0, v1);
                }
            }
    } else {
#pragma unroll
        for (int mt = 0; mt < 2; mt++)
#pragma unroll
            for (int half = 0; half < 2; half++) {
                int m = m0 + wm * 32 + mt * 16 + r + half * 8;
                int s = m & (S_LEN - 1);
                int bb = m >> 12;
#pragma unroll
                for (int nt = 0; nt < 8; nt++) {
                    int n_base = n0 + wn * 64 + nt * 8;
                    int h = n_base >> 8;
                    int d = (n_base & 255) + 2 * c;
                    int off = (d < 128) ? (192 + d) : (256 + d);
                    size_t obase = (((size_t)(bb * HEADS + h)) * S_LEN + s) * OUT_D;
                    *(float2*)(out + obase + off) =
                        make_float2(acc[mt][nt][half * 2], acc[mt][nt][half * 2 + 1]);
                }
            }
    }
}

// ---------------------------------------------------------------------------
// LayerNorm, register-resident row, shfl reductions (matches ref numerics)
// ---------------------------------------------------------------------------
__global__ __launch_bounds__(256)
void ln_kernel(const float* __restrict__ in, int ld, int ncols,
               const float* __restrict__ gamma, const float* __restrict__ beta,
               float* __restrict__ out)
{
    __shared__ float red[8], red2[8];
    int row = blockIdx.x;
    int tid = threadIdx.x;
    const float* src = in + (size_t)row * ld;

    float v[3] = {0.f, 0.f, 0.f};
#pragma unroll
    for (int i = 0; i < 3; i++) {
        int cc = tid + i * 256;
        if (cc < ncols) v[i] = src[cc];
    }
    float sum = v[0] + v[1] + v[2];
#pragma unroll
    for (int o = 16; o; o >>= 1) sum += __shfl_xor_sync(0xffffffffu, sum, o);
    if ((tid & 31) == 0) red[tid >> 5] = sum;
    __syncthreads();
    float tot = 0.f;
#pragma unroll
    for (int i = 0; i < 8; i++) tot += red[i];
    float mu = tot / (float)ncols;

    float sq = 0.f;
#pragma unroll
    for (int i = 0; i < 3; i++) {
        int cc = tid + i * 256;
        if (cc < ncols) { float d = v[i] - mu; sq += d * d; }
    }
#pragma unroll
    for (int o = 16; o; o >>= 1) sq += __shfl_xor_sync(0xffffffffu, sq, o);
    if ((tid & 31) == 0) red2[tid >> 5] = sq;
    __syncthreads();
    float tot2 = 0.f;
#pragma unroll
    for (int i = 0; i < 8; i++) tot2 += red2[i];
    float inv = rsqrtf(tot2 / (float)ncols + 1e-5f);

    float* dst = out + (size_t)row * ncols;
#pragma unroll
    for (int i = 0; i < 3; i++) {
        int cc = tid + i * 256;
        if (cc < ncols) dst[cc] = (v[i] - mu) * inv * gamma[cc] + beta[cc];
    }
}

// ---------------------------------------------------------------------------
// k_rot: RoPE on kv_c[:, 512:576] (pre-LN), broadcast to all 16 heads
// ---------------------------------------------------------------------------
__global__ void krot_kernel(const float* __restrict__ kvc,
                            const float* __restrict__ ctab,
                            const float* __restrict__ stab,
                            float* __restrict__ out)
{
    int t = blockIdx.x;
    int d = threadIdx.x;
    int s = t & (S_LEN - 1);
    int bb = t >> 12;
    const float* kr = kvc + (size_t)t * (KV_LR + QK_ROPE) + KV_LR;
    float x = kr[d];
    float p = kr[d ^ 32];
    int fidx = d & 31;
    float cv = ctab[s * 32 + fidx];
    float sv = stab[s * 32 + fidx];
    float res = x * cv + ((d < 32) ? -p : p) * sv;
#pragma unroll
    for (int h = 0; h < HEADS; h++)
        out[(((size_t)bb * HEADS + h) * S_LEN + s) * OUT_D + 320 + d] = res;
}

// ---------------------------------------------------------------------------
extern "C" void kernel_launch(void* const* d_in, const int* in_sizes, int n_in,
                              void* d_out, int out_size)
{
    const float* hidden  = (const float*)d_in[0];
    const float* w_qa    = (const float*)d_in[1];
    const float* b_qa    = (const float*)d_in[2];
    const float* g_qa_ln = (const float*)d_in[3];
    const float* b_qa_ln = (const float*)d_in[4];
    const float* w_qb    = (const float*)d_in[5];
    const float* b_qb    = (const float*)d_in[6];
    const float* w_kva   = (const float*)d_in[7];
    const float* b_kva   = (const float*)d_in[8];
    const float* g_kva_ln= (const float*)d_in[9];
    const float* b_kva_ln= (const float*)d_in[10];
    const float* w_kvb   = (const float*)d_in[11];
    const float* b_kvb   = (const float*)d_in[12];
    float* out = (float*)d_out;

    float *qc, *qln, *kvc, *kvln, *ct, *st;
    cudaGetSymbolAddress((void**)&qc,  g_qc);
    cudaGetSymbolAddress((void**)&qln, g_qln);
    cudaGetSymbolAddress((void**)&kvc, g_kvc);
    cudaGetSymbolAddress((void**)&kvln,g_kvln);
    cudaGetSymbolAddress((void**)&ct,  g_cos);
    cudaGetSymbolAddress((void**)&st,  g_sin);

    static bool attr_set = false;
    if (!attr_set) {
        cudaFuncSetAttribute(gemm_mma<0>, cudaFuncAttributeMaxDynamicSharedMemorySize, SMEM_BYTES);
        cudaFuncSetAttribute(gemm_mma<1>, cudaFuncAttributeMaxDynamicSharedMemorySize, SMEM_BYTES);
        cudaFuncSetAttribute(gemm_mma<2>, cudaFuncAttributeMaxDynamicSharedMemorySize, SMEM_BYTES);
        attr_set = true;
    }

    rope_table_kernel<<<(S_LEN * 32 + 255) / 256, 256>>>(ct, st);

    // down-projections
    gemm_mma<0><<<dim3(6, 64), 256, SMEM_BYTES>>>(hidden, w_qa, b_qa, qc,
                                                  NTOK, Q_LR, HID, nullptr, nullptr);
    gemm_mma<0><<<dim3(5, 64), 256, SMEM_BYTES>>>(hidden, w_kva, b_kva, kvc,
                                                  NTOK, KV_LR + QK_ROPE, HID, nullptr, nullptr);

    // layernorms
    ln_kernel<<<NTOK, 256>>>(qc,  Q_LR,            Q_LR,  g_qa_ln,  b_qa_ln,  qln);
    ln_kernel<<<NTOK, 256>>>(kvc, KV_LR + QK_ROPE, KV_LR, g_kva_ln, b_kva_ln, kvln);

    // up-projections with fused RoPE / scatter epilogues
    gemm_mma<1><<<dim3(24, 64), 256, SMEM_BYTES>>>(qln, w_qb, b_qb, out,
                                                   NTOK, HEADS * QK_HEAD, Q_LR, ct, st);
    gemm_mma<2><<<dim3(32, 64), 256, SMEM_BYTES>>>(kvln, w_kvb, b_kvb, out,
                                                   NTOK, HEADS * KV_HEAD, KV_LR, ct, st);

    // k_rot broadcast
    krot_kernel<<<NTOK, 64>>>(kvc, ct, st, out);
}

// round 5
// speedup vs baseline: 3.0360x; 2.1910x over previous
#include <cuda_runtime.h>
#include <cuda_bf16.h>
#include <math.h>

// Problem constants
#define B_SZ   2
#define S_LEN  4096
#define HID    2048
#define Q_LR   768
#define KV_LR  512
#define QK_ROPE 64
#define QK_NOPE 128
#define HEADS  16
#define QK_HEAD 192
#define KV_HEAD 256
#define NTOK   (B_SZ * S_LEN)   // 8192
#define OUT_D  512

typedef __nv_bfloat16 bf16;

// ---------------------------------------------------------------------------
// Scratch (device globals). bf16 planes in tiled+swizzled layout:
// elem(m,k) -> tile (m>>7, k>>6), within tile: row r=m&127 (128B per row),
// 16B chunk g=(k>>3)&7 stored at chunk (g ^ (r&7)), byte b=(k&7)*2.
// ---------------------------------------------------------------------------
__device__ __align__(1024) bf16 g_hid_hi [NTOK * HID];
__device__ __align__(1024) bf16 g_hid_mid[NTOK * HID];
__device__ __align__(1024) bf16 g_wqa_hi [768 * HID];
__device__ __align__(1024) bf16 g_wqa_mid[768 * HID];
__device__ __align__(1024) bf16 g_wkva_hi [768 * HID];   // padded 576->768
__device__ __align__(1024) bf16 g_wkva_mid[768 * HID];
__device__ __align__(1024) bf16 g_wqb_hi [3072 * Q_LR];
__device__ __align__(1024) bf16 g_wqb_mid[3072 * Q_LR];
__device__ __align__(1024) bf16 g_wkvb_hi [4096 * KV_LR];
__device__ __align__(1024) bf16 g_wkvb_mid[4096 * KV_LR];
__device__ __align__(1024) bf16 g_qln_hi [NTOK * Q_LR];
__device__ __align__(1024) bf16 g_qln_mid[NTOK * Q_LR];
__device__ __align__(1024) bf16 g_kvln_hi [NTOK * KV_LR];
__device__ __align__(1024) bf16 g_kvln_mid[NTOK * KV_LR];
__device__ float g_qc [NTOK * Q_LR];
__device__ float g_kvc[NTOK * (KV_LR + QK_ROPE)];
__device__ float g_cos[S_LEN * 32];
__device__ float g_sin[S_LEN * 32];

// plane index for element (m,k) given K (multiple of 64)
__device__ __forceinline__ size_t pidx(int m, int k, int K) {
    size_t tile = (size_t)((m >> 7) * (K >> 6) + (k >> 6)) * 8192;
    int r = m & 127;
    int g = (k >> 3) & 7;
    return tile + r * 64 + ((g ^ (r & 7)) << 3) + (k & 7);
}

// ---------------------------------------------------------------------------
// RoPE cos/sin table
// ---------------------------------------------------------------------------
__global__ void rope_table_kernel(float* __restrict__ ct, float* __restrict__ st) {
    int idx = blockIdx.x * blockDim.x + threadIdx.x;
    if (idx >= S_LEN * 32) return;
    int s = idx >> 5;
    int f = idx & 31;
    double inv = exp(-(double)f * (log(10000.0) / 32.0));
    double fr = (double)s * inv;
    ct[idx] = (float)cos(fr);
    st[idx] = (float)sin(fr);
}

// ---------------------------------------------------------------------------
// Split fp32 matrix [M,K] into hi/mid bf16 tiled planes [Mpad,K] (zero pad)
// One thread per 8-elem chunk.
// ---------------------------------------------------------------------------
__global__ void pack_split(const float* __restrict__ src, bf16* __restrict__ hi,
                           bf16* __restrict__ mid, int M, int Mpad, int K)
{
    long long c = (long long)blockIdx.x * blockDim.x + threadIdx.x;
    long long nch = (long long)Mpad * (K >> 3);
    if (c >= nch) return;
    int kc = (int)(c % (K >> 3));
    int m  = (int)(c / (K >> 3));
    int k0 = kc << 3;
    bf16 h[8], l[8];
#pragma unroll
    for (int j = 0; j < 8; j++) {
        float v = (m < M) ? src[(size_t)m * K + k0 + j] : 0.f;
        bf16 hh = __float2bfloat16(v);
        float rem = v - __bfloat162float(hh);
        h[j] = hh;
        l[j] = __float2bfloat16(rem);
    }
    size_t base = pidx(m, k0, K);
    *(uint4*)(hi + base)  = *(uint4*)h;
    *(uint4*)(mid + base) = *(uint4*)l;
}

// ---------------------------------------------------------------------------
// LayerNorm + split into bf16 planes (row-per-block)
// ---------------------------------------------------------------------------
__global__ __launch_bounds__(256)
void ln_pack(const float* __restrict__ in, int ld, int ncols,
             const float* __restrict__ gamma, const float* __restrict__ beta,
             bf16* __restrict__ hi, bf16* __restrict__ mid)
{
    __shared__ float row[768];
    __shared__ float red[8];
    int m = blockIdx.x;
    int tid = threadIdx.x;
    const float* src = in + (size_t)m * ld;

    float lsum = 0.f;
    for (int c = tid; c < ncols; c += 256) { float v = src[c]; row[c] = v; lsum += v; }
#pragma unroll
    for (int o = 16; o; o >>= 1) lsum += __shfl_xor_sync(0xffffffffu, lsum, o);
    if ((tid & 31) == 0) red[tid >> 5] = lsum;
    __syncthreads();
    float tot = 0.f;
#pragma unroll
    for (int i = 0; i < 8; i++) tot += red[i];
    float mu = tot / (float)ncols;
    __syncthreads();

    float lsq = 0.f;
    for (int c = tid; c < ncols; c += 256) { float d = row[c] - mu; lsq += d * d; }
#pragma unroll
    for (int o = 16; o; o >>= 1) lsq += __shfl_xor_sync(0xffffffffu, lsq, o);
    if ((tid & 31) == 0) red[tid >> 5] = lsq;
    __syncthreads();
    float tot2 = 0.f;
#pragma unroll
    for (int i = 0; i < 8; i++) tot2 += red[i];
    float inv = rsqrtf(tot2 / (float)ncols + 1e-5f);

    int nch = ncols >> 3;
    for (int ch = tid; ch < nch; ch += 256) {
        int c0 = ch << 3;
        bf16 h[8], l[8];
#pragma unroll
        for (int j = 0; j < 8; j++) {
            int c = c0 + j;
            float v = (row[c] - mu) * inv * gamma[c] + beta[c];
            bf16 hh = __float2bfloat16(v);
            h[j] = hh;
            l[j] = __float2bfloat16(v - __bfloat162float(hh));
        }
        size_t base = pidx(m, c0, ncols);
        *(uint4*)(hi + base)  = *(uint4*)h;
        *(uint4*)(mid + base) = *(uint4*)l;
    }
}

// ---------------------------------------------------------------------------
// PTX helpers
// ---------------------------------------------------------------------------
__device__ __forceinline__ void ldsm4(unsigned& r0, unsigned& r1, unsigned& r2,
                                      unsigned& r3, unsigned addr) {
    asm volatile("ldmatrix.sync.aligned.m8n8.x4.shared.b16 {%0,%1,%2,%3}, [%4];"
                 : "=r"(r0), "=r"(r1), "=r"(r2), "=r"(r3) : "r"(addr));
}
__device__ __forceinline__ void mma16(float* d, const unsigned* a, const unsigned* b) {
    asm volatile(
        "mma.sync.aligned.m16n8k16.row.col.f32.bf16.bf16.f32 "
        "{%0,%1,%2,%3},{%4,%5,%6,%7},{%8,%9},{%0,%1,%2,%3};"
        : "+f"(d[0]), "+f"(d[1]), "+f"(d[2]), "+f"(d[3])
        : "r"(a[0]), "r"(a[1]), "r"(a[2]), "r"(a[3]), "r"(b[0]), "r"(b[1]));
}
__device__ __forceinline__ void bulk_ld(unsigned dst, const void* src, unsigned mbar) {
    asm volatile(
        "cp.async.bulk.shared::cluster.global.mbarrier::complete_tx::bytes "
        "[%0], [%1], %2, [%3];"
        :: "r"(dst), "l"(src), "r"(16384u), "r"(mbar) : "memory");
}
__device__ __forceinline__ void mbar_init(unsigned mbar, unsigned cnt) {
    asm volatile("mbarrier.init.shared.b64 [%0], %1;" :: "r"(mbar), "r"(cnt) : "memory");
}
__device__ __forceinline__ void mbar_expect(unsigned mbar, unsigned bytes) {
    asm volatile("mbarrier.arrive.expect_tx.shared.b64 _, [%0], %1;"
                 :: "r"(mbar), "r"(bytes) : "memory");
}
__device__ __forceinline__ void mbar_wait(unsigned mbar, unsigned phase) {
    asm volatile(
        "{\n\t.reg .pred P;\n\t"
        "W%=:\n\t"
        "mbarrier.try_wait.parity.acquire.cta.shared::cta.b64 P, [%0], %1, 0x989680;\n\t"
        "@P bra D%=;\n\t"
        "bra W%=;\n\t"
        "D%=:\n\t}"
        :: "r"(mbar), "r"(phase) : "memory");
}

// ---------------------------------------------------------------------------
// bf16x2 3-pass GEMM, CTA 128(M) x 256(N), k-block 64, 2-stage bulk pipeline.
// A planes [M,K], B planes [Npad,K] (tiled/swizzled). 512 threads, 16 warps,
// warp tile 32x64 (wm=warp&3, wn=warp>>2). Accumulator layout = m16n8 std.
// EPI 0: C[m,n] (guard n<N).  EPI 1: q + RoPE scatter.  EPI 2: kv scatter.
// ---------------------------------------------------------------------------
#define STAGE_BYTES 98304u          // A(2x16K) + B(2x32K)
#define SMEM_TOTAL  (2 * STAGE_BYTES + 32)

template <int EPI>
__global__ __launch_bounds__(512, 1)
void gemm_bulk(const bf16* __restrict__ Ahi, const bf16* __restrict__ Amid,
               const bf16* __restrict__ Bhi, const bf16* __restrict__ Bmid,
               const float* __restrict__ bias, float* __restrict__ out,
               int N, int K,
               const float* __restrict__ ctab, const float* __restrict__ stab)
{
    extern __shared__ char smem[];
    const unsigned sbase = (unsigned)__cvta_generic_to_shared(smem);
    const unsigned mb0 = sbase + 2 * STAGE_BYTES;
    const unsigned mb1 = mb0 + 8;

    const int tid  = threadIdx.x;
    const int lane = tid & 31;
    const int warp = tid >> 5;
    const int wm = warp & 3;
    const int wn = warp >> 2;
    const int m0 = blockIdx.y * 128;
    const int n0 = blockIdx.x * 256;
    const int r = lane >> 2;
    const int c = lane & 3;
    const int KB = K >> 6;
    const int Ktiles = KB;

    if (tid == 0) {
        mbar_init(mb0, 1);
        mbar_init(mb1, 1);
        asm volatile("fence.proxy.async.shared::cta;" ::: "memory");
    }
    __syncthreads();

    float acc[2][8][4];
#pragma unroll
    for (int mt = 0; mt < 2; mt++)
#pragma unroll
        for (int nt = 0; nt < 8; nt++)
#pragma unroll
            for (int e = 0; e < 4; e++) acc[mt][nt][e] = 0.f;

    const int ntile0 = n0 >> 7;

    // prologue: stage 0
    if (tid == 0) {
        mbar_expect(mb0, STAGE_BYTES);
        size_t aoff = ((size_t)blockIdx.y * Ktiles) * 8192;
        bulk_ld(sbase, Ahi + aoff, mb0);
        bulk_ld(sbase + 16384, Amid + aoff, mb0);
        size_t b0o = ((size_t)ntile0 * Ktiles) * 8192;
        size_t b1o = ((size_t)(ntile0 + 1) * Ktiles) * 8192;
        bulk_ld(sbase + 32768, Bhi + b0o, mb0);
        bulk_ld(sbase + 49152, Bhi + b1o, mb0);
        bulk_ld(sbase + 65536, Bmid + b0o, mb0);
        bulk_ld(sbase + 81920, Bmid + b1o, mb0);
    }

    for (int kb = 0; kb < KB; kb++) {
        if (kb + 1 < KB) {
            __syncthreads();   // all warps done with buffer (kb+1)&1
            if (tid == 0) {
                unsigned mb = ((kb + 1) & 1) ? mb1 : mb0;
                unsigned sb = sbase + ((kb + 1) & 1) * STAGE_BYTES;
                mbar_expect(mb, STAGE_BYTES);
                size_t aoff = ((size_t)blockIdx.y * Ktiles + (kb + 1)) * 8192;
                bulk_ld(sb, Ahi + aoff, mb);
                bulk_ld(sb + 16384, Amid + aoff, mb);
                size_t b0o = ((size_t)ntile0 * Ktiles + (kb + 1)) * 8192;
                size_t b1o = ((size_t)(ntile0 + 1) * Ktiles + (kb + 1)) * 8192;
                bulk_ld(sb + 32768, Bhi + b0o, mb);
                bulk_ld(sb + 49152, Bhi + b1o, mb);
                bulk_ld(sb + 65536, Bmid + b0o, mb);
                bulk_ld(sb + 81920, Bmid + b1o, mb);
            }
        }
        mbar_wait((kb & 1) ? mb1 : mb0, (kb >> 1) & 1);

        const unsigned stage = sbase + (kb & 1) * STAGE_BYTES;
#pragma unroll
        for (int t = 0; t < 4; t++) {
            unsigned ah[2][4], al[2][4];
            const int gA = t * 2 + (lane >> 4);
#pragma unroll
            for (int mt = 0; mt < 2; mt++) {
                int rowA = wm * 32 + mt * 16 + (lane & 15);
                unsigned off = stage + rowA * 128 + (((unsigned)(gA ^ (rowA & 7))) << 4);
                ldsm4(ah[mt][0], ah[mt][1], ah[mt][2], ah[mt][3], off);
                ldsm4(al[mt][0], al[mt][1], al[mt][2], al[mt][3], off + 16384);
            }
            const int gB = t * 2 + ((lane >> 3) & 1);
            const int rB = (lane & 7) + ((lane & 16) >> 1);
#pragma unroll
            for (int np = 0; np < 4; np++) {
                int rowB = wn * 64 + np * 16 + rB;
                unsigned off = stage + 32768 + ((rowB >> 7) << 14)
                             + (rowB & 127) * 128 + (((unsigned)(gB ^ (rowB & 7))) << 4);
                unsigned bh[4], bl[4];
                ldsm4(bh[0], bh[1], bh[2], bh[3], off);
                ldsm4(bl[0], bl[1], bl[2], bl[3], off + 32768);
#pragma unroll
                for (int mt = 0; mt < 2; mt++) {
                    mma16(acc[mt][2 * np],     ah[mt], bh);
                    mma16(acc[mt][2 * np],     ah[mt], bl);
                    mma16(acc[mt][2 * np],     al[mt], bh);
                    mma16(acc[mt][2 * np + 1], ah[mt], bh + 2);
                    mma16(acc[mt][2 * np + 1], ah[mt], bl + 2);
                    mma16(acc[mt][2 * np + 1], al[mt], bh + 2);
                }
            }
        }
    }

    // ---- bias ----
#pragma unroll
    for (int nt = 0; nt < 8; nt++) {
        int nb = n0 + wn * 64 + nt * 8 + 2 * c;
        float b0 = 0.f, b1 = 0.f;
        if (EPI != 0 || nb < N)     b0 = bias[nb];
        if (EPI != 0 || nb + 1 < N) b1 = bias[nb + 1];
#pragma unroll
        for (int mt = 0; mt < 2; mt++) {
            acc[mt][nt][0] += b0; acc[mt][nt][1] += b1;
            acc[mt][nt][2] += b0; acc[mt][nt][3] += b1;
        }
    }

    // ---- epilogue ----
    if (EPI == 0) {
#pragma unroll
        for (int mt = 0; mt < 2; mt++)
#pragma unroll
            for (int half = 0; half < 2; half++) {
                int m = m0 + wm * 32 + mt * 16 + r + half * 8;
#pragma unroll
                for (int nt = 0; nt < 8; nt++) {
                    int n = n0 + wn * 64 + nt * 8 + 2 * c;
                    if (n < N)
                        *(float2*)(out + (size_t)m * N + n) =
                            make_float2(acc[mt][nt][half * 2], acc[mt][nt][half * 2 + 1]);
                }
            }
    } else if (EPI == 1) {
#pragma unroll
        for (int mt = 0; mt < 2; mt++)
#pragma unroll
            for (int half = 0; half < 2; half++) {
                int m = m0 + wm * 32 + mt * 16 + r + half * 8;
                int s = m & (S_LEN - 1);
                int bb = m >> 12;
#pragma unroll
                for (int nt = 0; nt < 8; nt++) {
                    int n_base = n0 + wn * 64 + nt * 8;
                    int h = ((n_base >> 6) * 43) >> 7;          // /192
                    int d0 = n_base - h * 192 + 2 * c;
                    size_t obase = (((size_t)(bb * HEADS + h)) * S_LEN + s) * OUT_D;
                    float v0 = acc[mt][nt][half * 2];
                    float v1 = acc[mt][nt][half * 2 + 1];
                    if (d0 >= 128) {
                        int fi = d0 & 31;
                        float c0 = ctab[s * 32 + fi],     s0 = stab[s * 32 + fi];
                        float c1 = ctab[s * 32 + fi + 1], s1 = stab[s * 32 + fi + 1];
                        float p0 = acc[mt][nt ^ 4][half * 2];
                        float p1 = acc[mt][nt ^ 4][half * 2 + 1];
                        float sg = (d0 & 32) ? 1.f : -1.f;
                        v0 = v0 * c0 + sg * p0 * s0;
                        v1 = v1 * c1 + sg * p1 * s1;
                    }
                    *(float2*)(out + obase + d0) = make_float2(v0, v1);
                }
            }
    } else {
#pragma unroll
        for (int mt = 0; mt < 2; mt++)
#pragma unroll
            for (int half = 0; half < 2; half++) {
                int m = m0 + wm * 32 + mt * 16 + r + half * 8;
                int s = m & (S_LEN - 1);
                int bb = m >> 12;
#pragma unroll
                for (int nt = 0; nt < 8; nt++) {
                    int n_base = n0 + wn * 64 + nt * 8;
                    int h = n_base >> 8;
                    int d = (n_base & 255) + 2 * c;
                    int off = (d < 128) ? (192 + d) : (256 + d);
                    size_t obase = (((size_t)(bb * HEADS + h)) * S_LEN + s) * OUT_D;
                    *(float2*)(out + obase + off) =
                        make_float2(acc[mt][nt][half * 2], acc[mt][nt][half * 2 + 1]);
                }
            }
    }
}

// ---------------------------------------------------------------------------
// k_rot: RoPE on kv_c[:, 512:576] (pre-LN), broadcast to all 16 heads
// ---------------------------------------------------------------------------
__global__ void krot_kernel(const float* __restrict__ kvc,
                            const float* __restrict__ ctab,
                            const float* __restrict__ stab,
                            float* __restrict__ out)
{
    int t = blockIdx.x;
    int d = threadIdx.x;
    int s = t & (S_LEN - 1);
    int bb = t >> 12;
    const float* kr = kvc + (size_t)t * (KV_LR + QK_ROPE) + KV_LR;
    float x = kr[d];
    float p = kr[d ^ 32];
    int fidx = d & 31;
    float cv = ctab[s * 32 + fidx];
    float sv = stab[s * 32 + fidx];
    float res = x * cv + ((d < 32) ? -p : p) * sv;
#pragma unroll
    for (int h = 0; h < HEADS; h++)
        out[(((size_t)bb * HEADS + h) * S_LEN + s) * OUT_D + 320 + d] = res;
}

// ---------------------------------------------------------------------------
extern "C" void kernel_launch(void* const* d_in, const int* in_sizes, int n_in,
                              void* d_out, int out_size)
{
    const float* hidden  = (const float*)d_in[0];
    const float* w_qa    = (const float*)d_in[1];
    const float* b_qa    = (const float*)d_in[2];
    const float* g_qa_ln = (const float*)d_in[3];
    const float* b_qa_ln = (const float*)d_in[4];
    const float* w_qb    = (const float*)d_in[5];
    const float* b_qb    = (const float*)d_in[6];
    const float* w_kva   = (const float*)d_in[7];
    const float* b_kva   = (const float*)d_in[8];
    const float* g_kva_ln= (const float*)d_in[9];
    const float* b_kva_ln= (const float*)d_in[10];
    const float* w_kvb   = (const float*)d_in[11];
    const float* b_kvb   = (const float*)d_in[12];
    float* out = (float*)d_out;

    bf16 *hid_hi, *hid_mid, *wqa_hi, *wqa_mid, *wkva_hi, *wkva_mid;
    bf16 *wqb_hi, *wqb_mid, *wkvb_hi, *wkvb_mid;
    bf16 *qln_hi, *qln_mid, *kvln_hi, *kvln_mid;
    float *qc, *kvc, *ct, *st;
    cudaGetSymbolAddress((void**)&hid_hi,  g_hid_hi);
    cudaGetSymbolAddress((void**)&hid_mid, g_hid_mid);
    cudaGetSymbolAddress((void**)&wqa_hi,  g_wqa_hi);
    cudaGetSymbolAddress((void**)&wqa_mid, g_wqa_mid);
    cudaGetSymbolAddress((void**)&wkva_hi, g_wkva_hi);
    cudaGetSymbolAddress((void**)&wkva_mid,g_wkva_mid);
    cudaGetSymbolAddress((void**)&wqb_hi,  g_wqb_hi);
    cudaGetSymbolAddress((void**)&wqb_mid, g_wqb_mid);
    cudaGetSymbolAddress((void**)&wkvb_hi, g_wkvb_hi);
    cudaGetSymbolAddress((void**)&wkvb_mid,g_wkvb_mid);
    cudaGetSymbolAddress((void**)&qln_hi,  g_qln_hi);
    cudaGetSymbolAddress((void**)&qln_mid, g_qln_mid);
    cudaGetSymbolAddress((void**)&kvln_hi, g_kvln_hi);
    cudaGetSymbolAddress((void**)&kvln_mid,g_kvln_mid);
    cudaGetSymbolAddress((void**)&qc,  g_qc);
    cudaGetSymbolAddress((void**)&kvc, g_kvc);
    cudaGetSymbolAddress((void**)&ct,  g_cos);
    cudaGetSymbolAddress((void**)&st,  g_sin);

    static bool attr_set = false;
    if (!attr_set) {
        cudaFuncSetAttribute(gemm_bulk<0>, cudaFuncAttributeMaxDynamicSharedMemorySize, SMEM_TOTAL);
        cudaFuncSetAttribute(gemm_bulk<1>, cudaFuncAttributeMaxDynamicSharedMemorySize, SMEM_TOTAL);
        cudaFuncSetAttribute(gemm_bulk<2>, cudaFuncAttributeMaxDynamicSharedMemorySize, SMEM_TOTAL);
        attr_set = true;
    }

    rope_table_kernel<<<(S_LEN * 32 + 255) / 256, 256>>>(ct, st);

    // pack inputs into bf16 hi/mid tiled planes
    {
        long long nch;
        nch = (long long)NTOK * (HID >> 3);
        pack_split<<<(unsigned)((nch + 255) / 256), 256>>>(hidden, hid_hi, hid_mid, NTOK, NTOK, HID);
        nch = (long long)768 * (HID >> 3);
        pack_split<<<(unsigned)((nch + 255) / 256), 256>>>(w_qa, wqa_hi, wqa_mid, 768, 768, HID);
        pack_split<<<(unsigned)((nch + 255) / 256), 256>>>(w_kva, wkva_hi, wkva_mid, 576, 768, HID);
        nch = (long long)3072 * (Q_LR >> 3);
        pack_split<<<(unsigned)((nch + 255) / 256), 256>>>(w_qb, wqb_hi, wqb_mid, 3072, 3072, Q_LR);
        nch = (long long)4096 * (KV_LR >> 3);
        pack_split<<<(unsigned)((nch + 255) / 256), 256>>>(w_kvb, wkvb_hi, wkvb_mid, 4096, 4096, KV_LR);
    }

    // down-projections
    gemm_bulk<0><<<dim3(3, 64), 512, SMEM_TOTAL>>>(hid_hi, hid_mid, wqa_hi, wqa_mid,
                                                   b_qa, qc, Q_LR, HID, nullptr, nullptr);
    gemm_bulk<0><<<dim3(3, 64), 512, SMEM_TOTAL>>>(hid_hi, hid_mid, wkva_hi, wkva_mid,
                                                   b_kva, kvc, KV_LR + QK_ROPE, HID, nullptr, nullptr);

    // layernorms + split
    ln_pack<<<NTOK, 256>>>(qc,  Q_LR,            Q_LR,  g_qa_ln,  b_qa_ln,  qln_hi,  qln_mid);
    ln_pack<<<NTOK, 256>>>(kvc, KV_LR + QK_ROPE, KV_LR, g_kva_ln, b_kva_ln, kvln_hi, kvln_mid);

    // up-projections with fused RoPE / scatter epilogues
    gemm_bulk<1><<<dim3(12, 64), 512, SMEM_TOTAL>>>(qln_hi, qln_mid, wqb_hi, wqb_mid,
                                                    b_qb, out, HEADS * QK_HEAD, Q_LR, ct, st);
    gemm_bulk<2><<<dim3(16, 64), 512, SMEM_TOTAL>>>(kvln_hi, kvln_mid, wkvb_hi, wkvb_mid,
                                                    b_kvb, out, HEADS * KV_HEAD, KV_LR, ct, st);

    // k_rot broadcast
    krot_kernel<<<NTOK, 64>>>(kvc, ct, st, out);
}

// round 10
// speedup vs baseline: 4.0604x; 1.3374x over previous
#include <cuda_runtime.h>
#include <cuda_fp16.h>
#include <math.h>
#include <stdint.h>

// Problem constants
#define B_SZ   2
#define S_LEN  4096
#define HID    2048
#define Q_LR   768
#define KV_LR  512
#define QK_ROPE 64
#define QK_NOPE 128
#define HEADS  16
#define QK_HEAD 192
#define KV_HEAD 256
#define NTOK   (B_SZ * S_LEN)   // 8192
#define OUT_D  512

typedef __half fp16;

// ---------------------------------------------------------------------------
// Device scratch. fp16 planes in tiled SW128 layout:
// elem(m,k) -> tile (m>>7, k>>6) [tile = 8192 elems = 128 rows x 128B],
// row r=m&127, 16B chunk g=(k>>3)&7 stored at chunk (g ^ (r&7)).
// Activations (A side): hi + lo planes. Weights (B side): hi plane only.
// ---------------------------------------------------------------------------
__device__ __align__(1024) fp16 g_hid_hi [NTOK * HID];
__device__ __align__(1024) fp16 g_hid_lo [NTOK * HID];
__device__ __align__(1024) fp16 g_wqa_hi [768 * HID];
__device__ __align__(1024) fp16 g_wkva_hi[768 * HID];    // padded 576->768
__device__ __align__(1024) fp16 g_wqb_hi [3072 * Q_LR];
__device__ __align__(1024) fp16 g_wkvb_hi[4096 * KV_LR];
__device__ __align__(1024) fp16 g_qln_hi [NTOK * Q_LR];
__device__ __align__(1024) fp16 g_qln_lo [NTOK * Q_LR];
__device__ __align__(1024) fp16 g_kvln_hi[NTOK * KV_LR];
__device__ __align__(1024) fp16 g_kvln_lo[NTOK * KV_LR];
__device__ float g_qc [NTOK * Q_LR];
__device__ float g_kvc[NTOK * (KV_LR + QK_ROPE)];
__device__ float g_cos[S_LEN * 32];
__device__ float g_sin[S_LEN * 32];

__device__ __forceinline__ size_t pidx(int m, int k, int K) {
    size_t tile = (size_t)((m >> 7) * (K >> 6) + (k >> 6)) * 8192;
    int r = m & 127;
    int g = (k >> 3) & 7;
    return tile + r * 64 + ((g ^ (r & 7)) << 3) + (k & 7);
}

// ---------------------------------------------------------------------------
__global__ void rope_table_kernel(float* __restrict__ ct, float* __restrict__ st) {
    int idx = blockIdx.x * blockDim.x + threadIdx.x;
    if (idx >= S_LEN * 32) return;
    int s = idx >> 5;
    int f = idx & 31;
    double inv = exp(-(double)f * (log(10000.0) / 32.0));
    double fr = (double)s * inv;
    ct[idx] = (float)cos(fr);
    st[idx] = (float)sin(fr);
}

// ---------------------------------------------------------------------------
// Pack fp32 [M,K] -> hi+lo fp16 tiled planes (activations)
// ---------------------------------------------------------------------------
__global__ void pack2(const float* __restrict__ src, fp16* __restrict__ hi,
                      fp16* __restrict__ lo, int M, int Mpad, int K)
{
    long long c = (long long)blockIdx.x * blockDim.x + threadIdx.x;
    long long nch = (long long)Mpad * (K >> 3);
    if (c >= nch) return;
    int kc = (int)(c % (K >> 3));
    int m  = (int)(c / (K >> 3));
    int k0 = kc << 3;
    fp16 h[8], l[8];
#pragma unroll
    for (int j = 0; j < 8; j++) {
        float v = (m < M) ? src[(size_t)m * K + k0 + j] : 0.f;
        fp16 hh = __float2half_rn(v);
        h[j] = hh;
        l[j] = __float2half_rn(v - __half2float(hh));
    }
    size_t base = pidx(m, k0, K);
    *(uint4*)(hi + base) = *(uint4*)h;
    *(uint4*)(lo + base) = *(uint4*)l;
}

// Pack fp32 [M,K] -> hi fp16 tiled plane only (weights)
__global__ void pack1(const float* __restrict__ src, fp16* __restrict__ hi,
                      int M, int Mpad, int K)
{
    long long c = (long long)blockIdx.x * blockDim.x + threadIdx.x;
    long long nch = (long long)Mpad * (K >> 3);
    if (c >= nch) return;
    int kc = (int)(c % (K >> 3));
    int m  = (int)(c / (K >> 3));
    int k0 = kc << 3;
    fp16 h[8];
#pragma unroll
    for (int j = 0; j < 8; j++) {
        float v = (m < M) ? src[(size_t)m * K + k0 + j] : 0.f;
        h[j] = __float2half_rn(v);
    }
    *(uint4*)(hi + pidx(m, k0, K)) = *(uint4*)h;
}

// ---------------------------------------------------------------------------
// LayerNorm + split into fp16 hi/lo planes (row-per-block)
// ---------------------------------------------------------------------------
__global__ __launch_bounds__(256)
void ln_pack(const float* __restrict__ in, int ld, int ncols,
             const float* __restrict__ gamma, const float* __restrict__ beta,
             fp16* __restrict__ hi, fp16* __restrict__ lo)
{
    __shared__ float row[768];
    __shared__ float red[8];
    int m = blockIdx.x;
    int tid = threadIdx.x;
    const float* src = in + (size_t)m * ld;

    float lsum = 0.f;
    for (int c = tid; c < ncols; c += 256) { float v = src[c]; row[c] = v; lsum += v; }
#pragma unroll
    for (int o = 16; o; o >>= 1) lsum += __shfl_xor_sync(0xffffffffu, lsum, o);
    if ((tid & 31) == 0) red[tid >> 5] = lsum;
    __syncthreads();
    float tot = 0.f;
#pragma unroll
    for (int i = 0; i < 8; i++) tot += red[i];
    float mu = tot / (float)ncols;
    __syncthreads();

    float lsq = 0.f;
    for (int c = tid; c < ncols; c += 256) { float d = row[c] - mu; lsq += d * d; }
#pragma unroll
    for (int o = 16; o; o >>= 1) lsq += __shfl_xor_sync(0xffffffffu, lsq, o);
    if ((tid & 31) == 0) red[tid >> 5] = lsq;
    __syncthreads();
    float tot2 = 0.f;
#pragma unroll
    for (int i = 0; i < 8; i++) tot2 += red[i];
    float inv = rsqrtf(tot2 / (float)ncols + 1e-5f);

    int nch = ncols >> 3;
    for (int ch = tid; ch < nch; ch += 256) {
        int c0 = ch << 3;
        fp16 h[8], l[8];
#pragma unroll
        for (int j = 0; j < 8; j++) {
            int c = c0 + j;
            float v = (row[c] - mu) * inv * gamma[c] + beta[c];
            fp16 hh = __float2half_rn(v);
            h[j] = hh;
            l[j] = __float2half_rn(v - __half2float(hh));
        }
        size_t base = pidx(m, c0, ncols);
        *(uint4*)(hi + base) = *(uint4*)h;
        *(uint4*)(lo + base) = *(uint4*)l;
    }
}

// ---------------------------------------------------------------------------
// PTX helpers
// ---------------------------------------------------------------------------
__device__ __forceinline__ void ldsm4(unsigned& r0, unsigned& r1, unsigned& r2,
                                      unsigned& r3, unsigned addr) {
    asm volatile("ldmatrix.sync.aligned.m8n8.x4.shared.b16 {%0,%1,%2,%3}, [%4];"
                 : "=r"(r0), "=r"(r1), "=r"(r2), "=r"(r3) : "r"(addr));
}
__device__ __forceinline__ void mma16(float* d, const unsigned* a, const unsigned* b) {
    asm volatile(
        "mma.sync.aligned.m16n8k16.row.col.f32.f16.f16.f32 "
        "{%0,%1,%2,%3},{%4,%5,%6,%7},{%8,%9},{%0,%1,%2,%3};"
        : "+f"(d[0]), "+f"(d[1]), "+f"(d[2]), "+f"(d[3])
        : "r"(a[0]), "r"(a[1]), "r"(a[2]), "r"(a[3]), "r"(b[0]), "r"(b[1]));
}
__device__ __forceinline__ void bulk_ld(unsigned dst, const void* src, unsigned mbar) {
    asm volatile(
        "cp.async.bulk.shared::cluster.global.mbarrier::complete_tx::bytes "
        "[%0], [%1], %2, [%3];"
        :: "r"(dst), "l"(src), "r"(16384u), "r"(mbar) : "memory");
}
__device__ __forceinline__ void mbar_init(unsigned mbar, unsigned cnt) {
    asm volatile("mbarrier.init.shared.b64 [%0], %1;" :: "r"(mbar), "r"(cnt) : "memory");
}
__device__ __forceinline__ void mbar_expect(unsigned mbar, unsigned bytes) {
    asm volatile("mbarrier.arrive.expect_tx.shared.b64 _, [%0], %1;"
                 :: "r"(mbar), "r"(bytes) : "memory");
}
__device__ __forceinline__ void mbar_arrive(unsigned mbar) {
    asm volatile("mbarrier.arrive.shared.b64 _, [%0];" :: "r"(mbar) : "memory");
}
__device__ __forceinline__ void mbar_wait(unsigned mbar, unsigned phase) {
    asm volatile(
        "{\n\t.reg .pred P;\n\t"
        "W%=:\n\t"
        "mbarrier.try_wait.parity.acquire.cta.shared::cta.b64 P, [%0], %1, 0x989680;\n\t"
        "@P bra D%=;\n\t"
        "bra W%=;\n\t"
        "D%=:\n\t}"
        :: "r"(mbar), "r"(phase) : "memory");
}

// ---------------------------------------------------------------------------
// fp16 2-pass GEMM (NT): C = (Ahi+Alo) @ Bhi^T + bias
// CTA tile 128(M) x 256(N), k-block 64, 3-stage bulk pipeline (64KB/stage:
// Ah 16K | Al 16K | Bh 32K). 544 threads: 16 compute warps (warp tile 32x64)
// + 1 producer warp driving cp.async.bulk against full/empty mbarriers.
// EPI 0: plain [M,N] store.  EPI 1: q + RoPE scatter.  EPI 2: kv scatter.
// ---------------------------------------------------------------------------
#define STAGE_BYTES 65536u
#define NSTAGE 3
#define MB_OFF (NSTAGE * STAGE_BYTES)          // 196608
#define SMEM_TOTAL (MB_OFF + 64)

template <int EPI>
__global__ __launch_bounds__(544, 1)
void gemm_hmma(const fp16* __restrict__ Ahi, const fp16* __restrict__ Alo,
               const fp16* __restrict__ Bhi,
               const float* __restrict__ bias, float* __restrict__ out,
               int N, int K,
               const float* __restrict__ ctab, const float* __restrict__ stab)
{
    extern __shared__ __align__(1024) char smem[];
    const unsigned sbase  = (unsigned)__cvta_generic_to_shared(smem);
    const unsigned fullb  = sbase + MB_OFF;        // 3 x 8B
    const unsigned emptyb = fullb + 24;            // 3 x 8B

    const int tid  = threadIdx.x;
    const int lane = tid & 31;
    const int wid  = tid >> 5;
    const int m0 = blockIdx.y * 128;
    const int n0 = blockIdx.x * 256;
    const int KB = K >> 6;
    const int ntile0 = n0 >> 7;

    if (tid == 0) {
#pragma unroll
        for (int s = 0; s < NSTAGE; s++) {
            mbar_init(fullb + s * 8, 1);
            mbar_init(emptyb + s * 8, 16);
        }
        asm volatile("fence.proxy.async.shared::cta;" ::: "memory");
    }
    __syncthreads();

    if (wid == 16) {
        // ---------------- producer warp ----------------
        if (lane == 0) {
            int eph[NSTAGE] = {0, 0, 0};
            int st = 0;
            for (int kb = 0; kb < KB; kb++) {
                unsigned stg = sbase + st * STAGE_BYTES;
                unsigned fb = fullb + st * 8;
                if (kb >= NSTAGE) { mbar_wait(emptyb + st * 8, eph[st]); eph[st] ^= 1; }
                mbar_expect(fb, STAGE_BYTES);
                size_t aoff = ((size_t)blockIdx.y * KB + kb) * 8192;
                bulk_ld(stg,          Ahi + aoff, fb);
                bulk_ld(stg + 16384,  Alo + aoff, fb);
                size_t b0 = ((size_t)ntile0 * KB + kb) * 8192;
                size_t b1 = ((size_t)(ntile0 + 1) * KB + kb) * 8192;
                bulk_ld(stg + 32768,  Bhi + b0, fb);
                bulk_ld(stg + 49152,  Bhi + b1, fb);
                if (++st == NSTAGE) st = 0;
            }
        }
        return;
    }

    // ---------------- compute warps ----------------
    const int wm = wid & 3;       // 0..3 along M (32 rows)
    const int wn = wid >> 2;      // 0..3 along N (64 cols)
    const int r = lane >> 2;
    const int c = lane & 3;

    float acc[2][8][4];
#pragma unroll
    for (int mt = 0; mt < 2; mt++)
#pragma unroll
        for (int nt = 0; nt < 8; nt++)
#pragma unroll
            for (int e = 0; e < 4; e++) acc[mt][nt][e] = 0.f;

    int fph[NSTAGE] = {0, 0, 0};
    int st = 0;
    for (int kb = 0; kb < KB; kb++) {
        mbar_wait(fullb + st * 8, fph[st]);
        fph[st] ^= 1;
        const unsigned stage = sbase + st * STAGE_BYTES;
#pragma unroll
        for (int t = 0; t < 4; t++) {
            unsigned ah[2][4], al[2][4];
            const int gA = t * 2 + (lane >> 4);
#pragma unroll
            for (int mt = 0; mt < 2; mt++) {
                int rowA = wm * 32 + mt * 16 + (lane & 15);
                unsigned off = stage + rowA * 128 + (((unsigned)(gA ^ (rowA & 7))) << 4);
                ldsm4(ah[mt][0], ah[mt][1], ah[mt][2], ah[mt][3], off);
                ldsm4(al[mt][0], al[mt][1], al[mt][2], al[mt][3], off + 16384);
            }
            const int gB = t * 2 + ((lane >> 3) & 1);
            const int rB = (lane & 7) + ((lane & 16) >> 1);
#pragma unroll
            for (int np = 0; np < 4; np++) {
                int rowB = wn * 64 + np * 16 + rB;
                unsigned off = stage + 32768 + ((rowB >> 7) << 14)
                             + (rowB & 127) * 128 + (((unsigned)(gB ^ (rowB & 7))) << 4);
                unsigned bh[4];
                ldsm4(bh[0], bh[1], bh[2], bh[3], off);
#pragma unroll
                for (int mt = 0; mt < 2; mt++) {
                    mma16(acc[mt][2 * np],     ah[mt], bh);
                    mma16(acc[mt][2 * np],     al[mt], bh);
                    mma16(acc[mt][2 * np + 1], ah[mt], bh + 2);
                    mma16(acc[mt][2 * np + 1], al[mt], bh + 2);
                }
            }
        }
        if (lane == 0) mbar_arrive(emptyb + st * 8);
        if (++st == NSTAGE) st = 0;
    }

    // ---- bias ----
#pragma unroll
    for (int nt = 0; nt < 8; nt++) {
        int nb = n0 + wn * 64 + nt * 8 + 2 * c;
        float b0 = 0.f, b1 = 0.f;
        if (EPI != 0 || nb < N)     b0 = bias[nb];
        if (EPI != 0 || nb + 1 < N) b1 = bias[nb + 1];
#pragma unroll
        for (int mt = 0; mt < 2; mt++) {
            acc[mt][nt][0] += b0; acc[mt][nt][1] += b1;
            acc[mt][nt][2] += b0; acc[mt][nt][3] += b1;
        }
    }

    // ---- epilogue ----
    if (EPI == 0) {
#pragma unroll
        for (int mt = 0; mt < 2; mt++)
#pragma unroll
            for (int half = 0; half < 2; half++) {
                int m = m0 + wm * 32 + mt * 16 + r + half * 8;
#pragma unroll
                for (int nt = 0; nt < 8; nt++) {
                    int n = n0 + wn * 64 + nt * 8 + 2 * c;
                    if (n < N)
                        *(float2*)(out + (size_t)m * N + n) =
                            make_float2(acc[mt][nt][half * 2], acc[mt][nt][half * 2 + 1]);
                }
            }
    } else if (EPI == 1) {
#pragma unroll
        for (int mt = 0; mt < 2; mt++)
#pragma unroll
            for (int half = 0; half < 2; half++) {
                int m = m0 + wm * 32 + mt * 16 + r + half * 8;
                int s = m & (S_LEN - 1);
                int bb = m >> 12;
#pragma unroll
                for (int nt = 0; nt < 8; nt++) {
                    int n_base = n0 + wn * 64 + nt * 8;
                    int h = ((n_base >> 6) * 43) >> 7;          // /192
                    int d0 = n_base - h * 192 + 2 * c;
                    size_t obase = (((size_t)(bb * HEADS + h)) * S_LEN + s) * OUT_D;
                    float v0 = acc[mt][nt][half * 2];
                    float v1 = acc[mt][nt][half * 2 + 1];
                    if (d0 >= 128) {
                        int fi = d0 & 31;
                        float c0 = ctab[s * 32 + fi],     s0 = stab[s * 32 + fi];
                        float c1 = ctab[s * 32 + fi + 1], s1 = stab[s * 32 + fi + 1];
                        float p0 = acc[mt][nt ^ 4][half * 2];
                        float p1 = acc[mt][nt ^ 4][half * 2 + 1];
                        float sg = (d0 & 32) ? 1.f : -1.f;
                        v0 = v0 * c0 + sg * p0 * s0;
                        v1 = v1 * c1 + sg * p1 * s1;
                    }
                    *(float2*)(out + obase + d0) = make_float2(v0, v1);
                }
            }
    } else {
#pragma unroll
        for (int mt = 0; mt < 2; mt++)
#pragma unroll
            for (int half = 0; half < 2; half++) {
                int m = m0 + wm * 32 + mt * 16 + r + half * 8;
                int s = m & (S_LEN - 1);
                int bb = m >> 12;
#pragma unroll
                for (int nt = 0; nt < 8; nt++) {
                    int n_base = n0 + wn * 64 + nt * 8;
                    int h = n_base >> 8;
                    int d = (n_base & 255) + 2 * c;
                    int off = (d < 128) ? (192 + d) : (256 + d);
                    size_t obase = (((size_t)(bb * HEADS + h)) * S_LEN + s) * OUT_D;
                    *(float2*)(out + obase + off) =
                        make_float2(acc[mt][nt][half * 2], acc[mt][nt][half * 2 + 1]);
                }
            }
    }
}

// ---------------------------------------------------------------------------
// k_rot: RoPE on kv_c[:, 512:576] (pre-LN), broadcast to all 16 heads
// ---------------------------------------------------------------------------
__global__ void krot_kernel(const float* __restrict__ kvc,
                            const float* __restrict__ ctab,
                            const float* __restrict__ stab,
                            float* __restrict__ out)
{
    int t = blockIdx.x;
    int d = threadIdx.x;
    int s = t & (S_LEN - 1);
    int bb = t >> 12;
    const float* kr = kvc + (size_t)t * (KV_LR + QK_ROPE) + KV_LR;
    float x = kr[d];
    float p = kr[d ^ 32];
    int fidx = d & 31;
    float cv = ctab[s * 32 + fidx];
    float sv = stab[s * 32 + fidx];
    float res = x * cv + ((d < 32) ? -p : p) * sv;
#pragma unroll
    for (int h = 0; h < HEADS; h++)
        out[(((size_t)bb * HEADS + h) * S_LEN + s) * OUT_D + 320 + d] = res;
}

// ---------------------------------------------------------------------------
extern "C" void kernel_launch(void* const* d_in, const int* in_sizes, int n_in,
                              void* d_out, int out_size)
{
    const float* hidden  = (const float*)d_in[0];
    const float* w_qa    = (const float*)d_in[1];
    const float* b_qa    = (const float*)d_in[2];
    const float* g_qa_ln = (const float*)d_in[3];
    const float* b_qa_ln = (const float*)d_in[4];
    const float* w_qb    = (const float*)d_in[5];
    const float* b_qb    = (const float*)d_in[6];
    const float* w_kva   = (const float*)d_in[7];
    const float* b_kva   = (const float*)d_in[8];
    const float* g_kva_ln= (const float*)d_in[9];
    const float* b_kva_ln= (const float*)d_in[10];
    const float* w_kvb   = (const float*)d_in[11];
    const float* b_kvb   = (const float*)d_in[12];
    float* out = (float*)d_out;

    fp16 *hid_hi, *hid_lo, *wqa_hi, *wkva_hi, *wqb_hi, *wkvb_hi;
    fp16 *qln_hi, *qln_lo, *kvln_hi, *kvln_lo;
    float *qc, *kvc, *ct, *st;
    cudaGetSymbolAddress((void**)&hid_hi,  g_hid_hi);
    cudaGetSymbolAddress((void**)&hid_lo,  g_hid_lo);
    cudaGetSymbolAddress((void**)&wqa_hi,  g_wqa_hi);
    cudaGetSymbolAddress((void**)&wkva_hi, g_wkva_hi);
    cudaGetSymbolAddress((void**)&wqb_hi,  g_wqb_hi);
    cudaGetSymbolAddress((void**)&wkvb_hi, g_wkvb_hi);
    cudaGetSymbolAddress((void**)&qln_hi,  g_qln_hi);
    cudaGetSymbolAddress((void**)&qln_lo,  g_qln_lo);
    cudaGetSymbolAddress((void**)&kvln_hi, g_kvln_hi);
    cudaGetSymbolAddress((void**)&kvln_lo, g_kvln_lo);
    cudaGetSymbolAddress((void**)&qc,  g_qc);
    cudaGetSymbolAddress((void**)&kvc, g_kvc);
    cudaGetSymbolAddress((void**)&ct,  g_cos);
    cudaGetSymbolAddress((void**)&st,  g_sin);

    static bool attr_set = false;
    if (!attr_set) {
        cudaFuncSetAttribute(gemm_hmma<0>, cudaFuncAttributeMaxDynamicSharedMemorySize, SMEM_TOTAL);
        cudaFuncSetAttribute(gemm_hmma<1>, cudaFuncAttributeMaxDynamicSharedMemorySize, SMEM_TOTAL);
        cudaFuncSetAttribute(gemm_hmma<2>, cudaFuncAttributeMaxDynamicSharedMemorySize, SMEM_TOTAL);
        attr_set = true;
    }

    rope_table_kernel<<<(S_LEN * 32 + 255) / 256, 256>>>(ct, st);

    // pack activations (hi+lo) and weights (hi only)
    {
        long long nch;
        nch = (long long)NTOK * (HID >> 3);
        pack2<<<(unsigned)((nch + 255) / 256), 256>>>(hidden, hid_hi, hid_lo, NTOK, NTOK, HID);
        nch = (long long)768 * (HID >> 3);
        pack1<<<(unsigned)((nch + 255) / 256), 256>>>(w_qa,  wqa_hi,  768, 768, HID);
        pack1<<<(unsigned)((nch + 255) / 256), 256>>>(w_kva, wkva_hi, 576, 768, HID);
        nch = (long long)3072 * (Q_LR >> 3);
        pack1<<<(unsigned)((nch + 255) / 256), 256>>>(w_qb,  wqb_hi,  3072, 3072, Q_LR);
        nch = (long long)4096 * (KV_LR >> 3);
        pack1<<<(unsigned)((nch + 255) / 256), 256>>>(w_kvb, wkvb_hi, 4096, 4096, KV_LR);
    }

    // down-projections (write fp32 scratch)
    gemm_hmma<0><<<dim3(3, 64), 544, SMEM_TOTAL>>>(hid_hi, hid_lo, wqa_hi,
                                                   b_qa, qc, Q_LR, HID, nullptr, nullptr);
    gemm_hmma<0><<<dim3(3, 64), 544, SMEM_TOTAL>>>(hid_hi, hid_lo, wkva_hi,
                                                   b_kva, kvc, KV_LR + QK_ROPE, HID, nullptr, nullptr);

    // layernorms + split into fp16 planes
    ln_pack<<<NTOK, 256>>>(qc,  Q_LR,            Q_LR,  g_qa_ln,  b_qa_ln,  qln_hi,  qln_lo);
    ln_pack<<<NTOK, 256>>>(kvc, KV_LR + QK_ROPE, KV_LR, g_kva_ln, b_kva_ln, kvln_hi, kvln_lo);

    // up-projections with fused RoPE / scatter epilogues
    gemm_hmma<1><<<dim3(12, 64), 544, SMEM_TOTAL>>>(qln_hi, qln_lo, wqb_hi,
                                                    b_qb, out, HEADS * QK_HEAD, Q_LR, ct, st);
    gemm_hmma<2><<<dim3(16, 64), 544, SMEM_TOTAL>>>(kvln_hi, kvln_lo, wkvb_hi,
                                                    b_kvb, out, HEADS * KV_HEAD, KV_LR, ct, st);

    // k_rot broadcast
    krot_kernel<<<NTOK, 64>>>(kvc, ct, st, out);
}

// round 11
// speedup vs baseline: 4.9343x; 1.2152x over previous
#include <cuda_runtime.h>
#include <cuda_fp16.h>
#include <math.h>
#include <stdint.h>

// Problem constants
#define B_SZ   2
#define S_LEN  4096
#define HID    2048
#define Q_LR   768
#define KV_LR  512
#define QK_ROPE 64
#define QK_NOPE 128
#define HEADS  16
#define QK_HEAD 192
#define KV_HEAD 256
#define NTOK   (B_SZ * S_LEN)   // 8192
#define OUT_D  512

typedef __half fp16;

// ---------------------------------------------------------------------------
// Device scratch. fp16 planes in tiled SW128 layout:
// elem(m,k) -> tile (m>>7, k>>6) [tile = 8192 elems = 128 rows x 128B],
// row r=m&127, 16B chunk g=(k>>3)&7 stored at chunk (g ^ (r&7)).
// hidden: hi only (down GEMMs single-pass). LN outputs: hi+lo (up 2-pass).
// Weights: hi only.
// ---------------------------------------------------------------------------
__device__ __align__(1024) fp16 g_hid_hi [NTOK * HID];
__device__ __align__(1024) fp16 g_wqa_hi [768 * HID];
__device__ __align__(1024) fp16 g_wkva_hi[768 * HID];    // padded 576->768
__device__ __align__(1024) fp16 g_wqb_hi [3072 * Q_LR];
__device__ __align__(1024) fp16 g_wkvb_hi[4096 * KV_LR];
__device__ __align__(1024) fp16 g_qln_hi [NTOK * Q_LR];
__device__ __align__(1024) fp16 g_qln_lo [NTOK * Q_LR];
__device__ __align__(1024) fp16 g_kvln_hi[NTOK * KV_LR];
__device__ __align__(1024) fp16 g_kvln_lo[NTOK * KV_LR];
__device__ float g_qc [NTOK * Q_LR];
__device__ float g_kvc[NTOK * (KV_LR + QK_ROPE)];
__device__ float g_cos[S_LEN * 32];
__device__ float g_sin[S_LEN * 32];

__device__ __forceinline__ size_t pidx(int m, int k, int K) {
    size_t tile = (size_t)((m >> 7) * (K >> 6) + (k >> 6)) * 8192;
    int r = m & 127;
    int g = (k >> 3) & 7;
    return tile + r * 64 + ((g ^ (r & 7)) << 3) + (k & 7);
}

// ---------------------------------------------------------------------------
__global__ void rope_table_kernel(float* __restrict__ ct, float* __restrict__ st) {
    int idx = blockIdx.x * blockDim.x + threadIdx.x;
    if (idx >= S_LEN * 32) return;
    int s = idx >> 5;
    int f = idx & 31;
    double inv = exp(-(double)f * (log(10000.0) / 32.0));
    double fr = (double)s * inv;
    ct[idx] = (float)cos(fr);
    st[idx] = (float)sin(fr);
}

// ---------------------------------------------------------------------------
// Pack fp32 [M,K] -> hi fp16 tiled plane (weights & hidden)
// ---------------------------------------------------------------------------
__global__ void pack1(const float* __restrict__ src, fp16* __restrict__ hi,
                      int M, int Mpad, int K)
{
    long long c = (long long)blockIdx.x * blockDim.x + threadIdx.x;
    long long nch = (long long)Mpad * (K >> 3);
    if (c >= nch) return;
    int kc = (int)(c % (K >> 3));
    int m  = (int)(c / (K >> 3));
    int k0 = kc << 3;
    fp16 h[8];
#pragma unroll
    for (int j = 0; j < 8; j++) {
        float v = (m < M) ? src[(size_t)m * K + k0 + j] : 0.f;
        h[j] = __float2half_rn(v);
    }
    *(uint4*)(hi + pidx(m, k0, K)) = *(uint4*)h;
}

// ---------------------------------------------------------------------------
// LayerNorm + split into fp16 hi/lo planes (row-per-block)
// ---------------------------------------------------------------------------
__global__ __launch_bounds__(256)
void ln_pack(const float* __restrict__ in, int ld, int ncols,
             const float* __restrict__ gamma, const float* __restrict__ beta,
             fp16* __restrict__ hi, fp16* __restrict__ lo)
{
    __shared__ float row[768];
    __shared__ float red[8];
    int m = blockIdx.x;
    int tid = threadIdx.x;
    const float* src = in + (size_t)m * ld;

    float lsum = 0.f;
    for (int c = tid; c < ncols; c += 256) { float v = src[c]; row[c] = v; lsum += v; }
#pragma unroll
    for (int o = 16; o; o >>= 1) lsum += __shfl_xor_sync(0xffffffffu, lsum, o);
    if ((tid & 31) == 0) red[tid >> 5] = lsum;
    __syncthreads();
    float tot = 0.f;
#pragma unroll
    for (int i = 0; i < 8; i++) tot += red[i];
    float mu = tot / (float)ncols;
    __syncthreads();

    float lsq = 0.f;
    for (int c = tid; c < ncols; c += 256) { float d = row[c] - mu; lsq += d * d; }
#pragma unroll
    for (int o = 16; o; o >>= 1) lsq += __shfl_xor_sync(0xffffffffu, lsq, o);
    if ((tid & 31) == 0) red[tid >> 5] = lsq;
    __syncthreads();
    float tot2 = 0.f;
#pragma unroll
    for (int i = 0; i < 8; i++) tot2 += red[i];
    float inv = rsqrtf(tot2 / (float)ncols + 1e-5f);

    int nch = ncols >> 3;
    for (int ch = tid; ch < nch; ch += 256) {
        int c0 = ch << 3;
        fp16 h[8], l[8];
#pragma unroll
        for (int j = 0; j < 8; j++) {
            int c = c0 + j;
            float v = (row[c] - mu) * inv * gamma[c] + beta[c];
            fp16 hh = __float2half_rn(v);
            h[j] = hh;
            l[j] = __float2half_rn(v - __half2float(hh));
        }
        size_t base = pidx(m, c0, ncols);
        *(uint4*)(hi + base) = *(uint4*)h;
        *(uint4*)(lo + base) = *(uint4*)l;
    }
}

// ---------------------------------------------------------------------------
// PTX helpers
// ---------------------------------------------------------------------------
__device__ __forceinline__ void ldsm4(unsigned& r0, unsigned& r1, unsigned& r2,
                                      unsigned& r3, unsigned addr) {
    asm volatile("ldmatrix.sync.aligned.m8n8.x4.shared.b16 {%0,%1,%2,%3}, [%4];"
                 : "=r"(r0), "=r"(r1), "=r"(r2), "=r"(r3) : "r"(addr));
}
__device__ __forceinline__ void mma16(float* d, const unsigned* a, const unsigned* b) {
    asm volatile(
        "mma.sync.aligned.m16n8k16.row.col.f32.f16.f16.f32 "
        "{%0,%1,%2,%3},{%4,%5,%6,%7},{%8,%9},{%0,%1,%2,%3};"
        : "+f"(d[0]), "+f"(d[1]), "+f"(d[2]), "+f"(d[3])
        : "r"(a[0]), "r"(a[1]), "r"(a[2]), "r"(a[3]), "r"(b[0]), "r"(b[1]));
}
__device__ __forceinline__ void bulk_ld(unsigned dst, const void* src, unsigned mbar) {
    asm volatile(
        "cp.async.bulk.shared::cluster.global.mbarrier::complete_tx::bytes "
        "[%0], [%1], %2, [%3];"
        :: "r"(dst), "l"(src), "r"(16384u), "r"(mbar) : "memory");
}
__device__ __forceinline__ void mbar_init(unsigned mbar, unsigned cnt) {
    asm volatile("mbarrier.init.shared.b64 [%0], %1;" :: "r"(mbar), "r"(cnt) : "memory");
}
__device__ __forceinline__ void mbar_expect(unsigned mbar, unsigned bytes) {
    asm volatile("mbarrier.arrive.expect_tx.shared.b64 _, [%0], %1;"
                 :: "r"(mbar), "r"(bytes) : "memory");
}
__device__ __forceinline__ void mbar_arrive(unsigned mbar) {
    asm volatile("mbarrier.arrive.shared.b64 _, [%0];" :: "r"(mbar) : "memory");
}
__device__ __forceinline__ void mbar_wait(unsigned mbar, unsigned phase) {
    asm volatile(
        "{\n\t.reg .pred P;\n\t"
        "W%=:\n\t"
        "mbarrier.try_wait.parity.acquire.cta.shared::cta.b64 P, [%0], %1, 0x989680;\n\t"
        "@P bra D%=;\n\t"
        "bra W%=;\n\t"
        "D%=:\n\t}"
        :: "r"(mbar), "r"(phase) : "memory");
}

// ---------------------------------------------------------------------------
// fp16 GEMM (NT): C = (Ahi [+Alo]) @ Bhi^T + bias
// CTA tile 128(M) x 256(N), k-block 64, bulk-copy ring pipeline.
// PASSES=2: stage 64KB (Ah 16K | Al 16K | Bh 32K), 3 stages.
// PASSES=1: stage 48KB (Ah 16K | Bh 32K), 4 stages.
// 544 threads: 16 compute warps (warp tile 32x64) + 1 producer warp.
// EPI 0: plain [M,N] store.  EPI 1: q + RoPE scatter.  EPI 2: kv scatter.
// ---------------------------------------------------------------------------
#define SMEM_TOTAL (196608 + 64)

template <int EPI, int PASSES>
__global__ __launch_bounds__(544, 1)
void gemm_hmma(const fp16* __restrict__ Ahi, const fp16* __restrict__ Alo,
               const fp16* __restrict__ Bhi,
               const float* __restrict__ bias, float* __restrict__ out,
               int N, int K,
               const float* __restrict__ ctab, const float* __restrict__ stab)
{
    constexpr unsigned STAGE = (PASSES == 2) ? 65536u : 49152u;
    constexpr int NST = (PASSES == 2) ? 3 : 4;
    constexpr unsigned BOFF = (PASSES == 2) ? 32768u : 16384u;

    extern __shared__ __align__(1024) char smem[];
    const unsigned sbase  = (unsigned)__cvta_generic_to_shared(smem);
    const unsigned fullb  = sbase + 196608;        // NST x 8B
    const unsigned emptyb = fullb + 32;            // NST x 8B

    const int tid  = threadIdx.x;
    const int lane = tid & 31;
    const int wid  = tid >> 5;
    const int m0 = blockIdx.y * 128;
    const int n0 = blockIdx.x * 256;
    const int KB = K >> 6;
    const int ntile0 = n0 >> 7;

    if (tid == 0) {
#pragma unroll
        for (int s = 0; s < NST; s++) {
            mbar_init(fullb + s * 8, 1);
            mbar_init(emptyb + s * 8, 16);
        }
        asm volatile("fence.proxy.async.shared::cta;" ::: "memory");
    }
    __syncthreads();

    if (wid == 16) {
        // ---------------- producer warp ----------------
        if (lane == 0) {
            int eph[NST];
#pragma unroll
            for (int s = 0; s < NST; s++) eph[s] = 0;
            int st = 0;
            for (int kb = 0; kb < KB; kb++) {
                unsigned stg = sbase + st * STAGE;
                unsigned fb = fullb + st * 8;
                if (kb >= NST) { mbar_wait(emptyb + st * 8, eph[st]); eph[st] ^= 1; }
                mbar_expect(fb, STAGE);
                size_t aoff = ((size_t)blockIdx.y * KB + kb) * 8192;
                bulk_ld(stg, Ahi + aoff, fb);
                if (PASSES == 2) bulk_ld(stg + 16384, Alo + aoff, fb);
                size_t b0 = ((size_t)ntile0 * KB + kb) * 8192;
                size_t b1 = ((size_t)(ntile0 + 1) * KB + kb) * 8192;
                bulk_ld(stg + BOFF,          Bhi + b0, fb);
                bulk_ld(stg + BOFF + 16384,  Bhi + b1, fb);
                if (++st == NST) st = 0;
            }
        }
        return;
    }

    // ---------------- compute warps ----------------
    const int wm = wid & 3;       // 0..3 along M (32 rows)
    const int wn = wid >> 2;      // 0..3 along N (64 cols)
    const int r = lane >> 2;
    const int c = lane & 3;

    float acc[2][8][4];
#pragma unroll
    for (int mt = 0; mt < 2; mt++)
#pragma unroll
        for (int nt = 0; nt < 8; nt++)
#pragma unroll
            for (int e = 0; e < 4; e++) acc[mt][nt][e] = 0.f;

    int fph[NST];
#pragma unroll
    for (int s = 0; s < NST; s++) fph[s] = 0;
    int st = 0;
    for (int kb = 0; kb < KB; kb++) {
        mbar_wait(fullb + st * 8, fph[st]);
        fph[st] ^= 1;
        const unsigned stage = sbase + st * STAGE;
#pragma unroll
        for (int t = 0; t < 4; t++) {
            unsigned ah[2][4], al[2][4];
            const int gA = t * 2 + (lane >> 4);
#pragma unroll
            for (int mt = 0; mt < 2; mt++) {
                int rowA = wm * 32 + mt * 16 + (lane & 15);
                unsigned off = stage + rowA * 128 + (((unsigned)(gA ^ (rowA & 7))) << 4);
                ldsm4(ah[mt][0], ah[mt][1], ah[mt][2], ah[mt][3], off);
                if (PASSES == 2)
                    ldsm4(al[mt][0], al[mt][1], al[mt][2], al[mt][3], off + 16384);
            }
            const int gB = t * 2 + ((lane >> 3) & 1);
            const int rB = (lane & 7) + ((lane & 16) >> 1);
#pragma unroll
            for (int np = 0; np < 4; np++) {
                int rowB = wn * 64 + np * 16 + rB;
                unsigned off = stage + BOFF + ((rowB >> 7) << 14)
                             + (rowB & 127) * 128 + (((unsigned)(gB ^ (rowB & 7))) << 4);
                unsigned bh[4];
                ldsm4(bh[0], bh[1], bh[2], bh[3], off);
#pragma unroll
                for (int mt = 0; mt < 2; mt++) {
                    mma16(acc[mt][2 * np],     ah[mt], bh);
                    if (PASSES == 2) mma16(acc[mt][2 * np], al[mt], bh);
                    mma16(acc[mt][2 * np + 1], ah[mt], bh + 2);
                    if (PASSES == 2) mma16(acc[mt][2 * np + 1], al[mt], bh + 2);
                }
            }
        }
        if (lane == 0) mbar_arrive(emptyb + st * 8);
        if (++st == NST) st = 0;
    }

    // ---- bias ----
#pragma unroll
    for (int nt = 0; nt < 8; nt++) {
        int nb = n0 + wn * 64 + nt * 8 + 2 * c;
        float b0 = 0.f, b1 = 0.f;
        if (EPI != 0 || nb < N)     b0 = bias[nb];
        if (EPI != 0 || nb + 1 < N) b1 = bias[nb + 1];
#pragma unroll
        for (int mt = 0; mt < 2; mt++) {
            acc[mt][nt][0] += b0; acc[mt][nt][1] += b1;
            acc[mt][nt][2] += b0; acc[mt][nt][3] += b1;
        }
    }

    // ---- epilogue ----
    if (EPI == 0) {
#pragma unroll
        for (int mt = 0; mt < 2; mt++)
#pragma unroll
            for (int half = 0; half < 2; half++) {
                int m = m0 + wm * 32 + mt * 16 + r + half * 8;
#pragma unroll
                for (int nt = 0; nt < 8; nt++) {
                    int n = n0 + wn * 64 + nt * 8 + 2 * c;
                    if (n < N)
                        *(float2*)(out + (size_t)m * N + n) =
                            make_float2(acc[mt][nt][half * 2], acc[mt][nt][half * 2 + 1]);
                }
            }
    } else if (EPI == 1) {
#pragma unroll
        for (int mt = 0; mt < 2; mt++)
#pragma unroll
            for (int half = 0; half < 2; half++) {
                int m = m0 + wm * 32 + mt * 16 + r + half * 8;
                int s = m & (S_LEN - 1);
                int bb = m >> 12;
#pragma unroll
                for (int nt = 0; nt < 8; nt++) {
                    int n_base = n0 + wn * 64 + nt * 8;
                    int h = ((n_base >> 6) * 43) >> 7;          // /192
                    int d0 = n_base - h * 192 + 2 * c;
                    size_t obase = (((size_t)(bb * HEADS + h)) * S_LEN + s) * OUT_D;
                    float v0 = acc[mt][nt][half * 2];
                    float v1 = acc[mt][nt][half * 2 + 1];
                    if (d0 >= 128) {
                        int fi = d0 & 31;
                        float c0 = ctab[s * 32 + fi],     s0 = stab[s * 32 + fi];
                        float c1 = ctab[s * 32 + fi + 1], s1 = stab[s * 32 + fi + 1];
                        float p0 = acc[mt][nt ^ 4][half * 2];
                        float p1 = acc[mt][nt ^ 4][half * 2 + 1];
                        float sg = (d0 & 32) ? 1.f : -1.f;
                        v0 = v0 * c0 + sg * p0 * s0;
                        v1 = v1 * c1 + sg * p1 * s1;
                    }
                    *(float2*)(out + obase + d0) = make_float2(v0, v1);
                }
            }
    } else {
#pragma unroll
        for (int mt = 0; mt < 2; mt++)
#pragma unroll
            for (int half = 0; half < 2; half++) {
                int m = m0 + wm * 32 + mt * 16 + r + half * 8;
                int s = m & (S_LEN - 1);
                int bb = m >> 12;
#pragma unroll
                for (int nt = 0; nt < 8; nt++) {
                    int n_base = n0 + wn * 64 + nt * 8;
                    int h = n_base >> 8;
                    int d = (n_base & 255) + 2 * c;
                    int off = (d < 128) ? (192 + d) : (256 + d);
                    size_t obase = (((size_t)(bb * HEADS + h)) * S_LEN + s) * OUT_D;
                    *(float2*)(out + obase + off) =
                        make_float2(acc[mt][nt][half * 2], acc[mt][nt][half * 2 + 1]);
                }
            }
    }
}

// ---------------------------------------------------------------------------
// k_rot: RoPE on kv_c[:, 512:576] (pre-LN), broadcast to all 16 heads
// ---------------------------------------------------------------------------
__global__ void krot_kernel(const float* __restrict__ kvc,
                            const float* __restrict__ ctab,
                            const float* __restrict__ stab,
                            float* __restrict__ out)
{
    int t = blockIdx.x;
    int d = threadIdx.x;
    int s = t & (S_LEN - 1);
    int bb = t >> 12;
    const float* kr = kvc + (size_t)t * (KV_LR + QK_ROPE) + KV_LR;
    float x = kr[d];
    float p = kr[d ^ 32];
    int fidx = d & 31;
    float cv = ctab[s * 32 + fidx];
    float sv = stab[s * 32 + fidx];
    float res = x * cv + ((d < 32) ? -p : p) * sv;
#pragma unroll
    for (int h = 0; h < HEADS; h++)
        out[(((size_t)bb * HEADS + h) * S_LEN + s) * OUT_D + 320 + d] = res;
}

// ---------------------------------------------------------------------------
extern "C" void kernel_launch(void* const* d_in, const int* in_sizes, int n_in,
                              void* d_out, int out_size)
{
    const float* hidden  = (const float*)d_in[0];
    const float* w_qa    = (const float*)d_in[1];
    const float* b_qa    = (const float*)d_in[2];
    const float* g_qa_ln = (const float*)d_in[3];
    const float* b_qa_ln = (const float*)d_in[4];
    const float* w_qb    = (const float*)d_in[5];
    const float* b_qb    = (const float*)d_in[6];
    const float* w_kva   = (const float*)d_in[7];
    const float* b_kva   = (const float*)d_in[8];
    const float* g_kva_ln= (const float*)d_in[9];
    const float* b_kva_ln= (const float*)d_in[10];
    const float* w_kvb   = (const float*)d_in[11];
    const float* b_kvb   = (const float*)d_in[12];
    float* out = (float*)d_out;

    fp16 *hid_hi, *wqa_hi, *wkva_hi, *wqb_hi, *wkvb_hi;
    fp16 *qln_hi, *qln_lo, *kvln_hi, *kvln_lo;
    float *qc, *kvc, *ct, *st;
    cudaGetSymbolAddress((void**)&hid_hi,  g_hid_hi);
    cudaGetSymbolAddress((void**)&wqa_hi,  g_wqa_hi);
    cudaGetSymbolAddress((void**)&wkva_hi, g_wkva_hi);
    cudaGetSymbolAddress((void**)&wqb_hi,  g_wqb_hi);
    cudaGetSymbolAddress((void**)&wkvb_hi, g_wkvb_hi);
    cudaGetSymbolAddress((void**)&qln_hi,  g_qln_hi);
    cudaGetSymbolAddress((void**)&qln_lo,  g_qln_lo);
    cudaGetSymbolAddress((void**)&kvln_hi, g_kvln_hi);
    cudaGetSymbolAddress((void**)&kvln_lo, g_kvln_lo);
    cudaGetSymbolAddress((void**)&qc,  g_qc);
    cudaGetSymbolAddress((void**)&kvc, g_kvc);
    cudaGetSymbolAddress((void**)&ct,  g_cos);
    cudaGetSymbolAddress((void**)&st,  g_sin);

    static bool attr_set = false;
    if (!attr_set) {
        cudaFuncSetAttribute((const void*)gemm_hmma<0,1>, cudaFuncAttributeMaxDynamicSharedMemorySize, SMEM_TOTAL);
        cudaFuncSetAttribute((const void*)gemm_hmma<1,2>, cudaFuncAttributeMaxDynamicSharedMemorySize, SMEM_TOTAL);
        cudaFuncSetAttribute((const void*)gemm_hmma<2,2>, cudaFuncAttributeMaxDynamicSharedMemorySize, SMEM_TOTAL);
        attr_set = true;
    }

    rope_table_kernel<<<(S_LEN * 32 + 255) / 256, 256>>>(ct, st);

    // pack hidden (hi only) and weights (hi only)
    {
        long long nch;
        nch = (long long)NTOK * (HID >> 3);
        pack1<<<(unsigned)((nch + 255) / 256), 256>>>(hidden, hid_hi, NTOK, NTOK, HID);
        nch = (long long)768 * (HID >> 3);
        pack1<<<(unsigned)((nch + 255) / 256), 256>>>(w_qa,  wqa_hi,  768, 768, HID);
        pack1<<<(unsigned)((nch + 255) / 256), 256>>>(w_kva, wkva_hi, 576, 768, HID);
        nch = (long long)3072 * (Q_LR >> 3);
        pack1<<<(unsigned)((nch + 255) / 256), 256>>>(w_qb,  wqb_hi,  3072, 3072, Q_LR);
        nch = (long long)4096 * (KV_LR >> 3);
        pack1<<<(unsigned)((nch + 255) / 256), 256>>>(w_kvb, wkvb_hi, 4096, 4096, KV_LR);
    }

    // down-projections: single-pass fp16 (feeds LN; error renormalized)
    gemm_hmma<0,1><<<dim3(3, 64), 544, SMEM_TOTAL>>>(hid_hi, nullptr, wqa_hi,
                                                     b_qa, qc, Q_LR, HID, nullptr, nullptr);
    gemm_hmma<0,1><<<dim3(3, 64), 544, SMEM_TOTAL>>>(hid_hi, nullptr, wkva_hi,
                                                     b_kva, kvc, KV_LR + QK_ROPE, HID, nullptr, nullptr);

    // layernorms + split into fp16 hi/lo planes
    ln_pack<<<NTOK, 256>>>(qc,  Q_LR,            Q_LR,  g_qa_ln,  b_qa_ln,  qln_hi,  qln_lo);
    ln_pack<<<NTOK, 256>>>(kvc, KV_LR + QK_ROPE, KV_LR, g_kva_ln, b_kva_ln, kvln_hi, kvln_lo);

    // up-projections: 2-pass activations, fused RoPE / scatter epilogues
    gemm_hmma<1,2><<<dim3(12, 64), 544, SMEM_TOTAL>>>(qln_hi, qln_lo, wqb_hi,
                                                      b_qb, out, HEADS * QK_HEAD, Q_LR, ct, st);
    gemm_hmma<2,2><<<dim3(16, 64), 544, SMEM_TOTAL>>>(kvln_hi, kvln_lo, wkvb_hi,
                                                      b_kvb, out, HEADS * KV_HEAD, KV_LR, ct, st);

    // k_rot broadcast
    krot_kernel<<<NTOK, 64>>>(kvc, ct, st, out);
}

// round 12
// speedup vs baseline: 6.3108x; 1.2790x over previous
#include <cuda_runtime.h>
#include <cuda_fp16.h>
#include <math.h>
#include <stdint.h>

// Problem constants
#define B_SZ   2
#define S_LEN  4096
#define HID    2048
#define Q_LR   768
#define KV_LR  512
#define QK_ROPE 64
#define QK_NOPE 128
#define HEADS  16
#define QK_HEAD 192
#define KV_HEAD 256
#define NTOK   (B_SZ * S_LEN)   // 8192
#define OUT_D  512

typedef __half fp16;

// ---------------------------------------------------------------------------
// Device scratch. fp16 planes in tiled SW128 layout:
// elem(m,k) -> tile (m>>7, k>>6) [tile = 8192 elems = 128 rows x 128B],
// row r=m&127, 16B chunk g=(k>>3)&7 stored at chunk (g ^ (r&7)).
// All GEMMs single-pass fp16 (hi planes only).
// ---------------------------------------------------------------------------
__device__ __align__(1024) fp16 g_hid_hi [NTOK * HID];
__device__ __align__(1024) fp16 g_wqa_hi [768 * HID];
__device__ __align__(1024) fp16 g_wkva_hi[768 * HID];    // padded 576->768
__device__ __align__(1024) fp16 g_wqb_hi [3072 * Q_LR];
__device__ __align__(1024) fp16 g_wkvb_hi[4096 * KV_LR];
__device__ __align__(1024) fp16 g_qln_hi [NTOK * Q_LR];
__device__ __align__(1024) fp16 g_kvln_hi[NTOK * KV_LR];
__device__ float g_qc [NTOK * Q_LR];
__device__ float g_kvc[NTOK * (KV_LR + QK_ROPE)];
__device__ float g_cos[S_LEN * 32];
__device__ float g_sin[S_LEN * 32];

__device__ __forceinline__ size_t pidx(int m, int k, int K) {
    size_t tile = (size_t)((m >> 7) * (K >> 6) + (k >> 6)) * 8192;
    int r = m & 127;
    int g = (k >> 3) & 7;
    return tile + r * 64 + ((g ^ (r & 7)) << 3) + (k & 7);
}

// ---------------------------------------------------------------------------
__global__ void rope_table_kernel(float* __restrict__ ct, float* __restrict__ st) {
    int idx = blockIdx.x * blockDim.x + threadIdx.x;
    if (idx >= S_LEN * 32) return;
    int s = idx >> 5;
    int f = idx & 31;
    double inv = exp(-(double)f * (log(10000.0) / 32.0));
    double fr = (double)s * inv;
    ct[idx] = (float)cos(fr);
    st[idx] = (float)sin(fr);
}

// ---------------------------------------------------------------------------
// Pack fp32 [M,K] -> hi fp16 tiled plane
// ---------------------------------------------------------------------------
__global__ void pack1(const float* __restrict__ src, fp16* __restrict__ hi,
                      int M, int Mpad, int K)
{
    long long c = (long long)blockIdx.x * blockDim.x + threadIdx.x;
    long long nch = (long long)Mpad * (K >> 3);
    if (c >= nch) return;
    int kc = (int)(c % (K >> 3));
    int m  = (int)(c / (K >> 3));
    int k0 = kc << 3;
    fp16 h[8];
#pragma unroll
    for (int j = 0; j < 8; j++) {
        float v = (m < M) ? src[(size_t)m * K + k0 + j] : 0.f;
        h[j] = __float2half_rn(v);
    }
    *(uint4*)(hi + pidx(m, k0, K)) = *(uint4*)h;
}

// ---------------------------------------------------------------------------
// LayerNorm + pack into fp16 hi plane (row-per-block)
// ---------------------------------------------------------------------------
__global__ __launch_bounds__(256)
void ln_pack(const float* __restrict__ in, int ld, int ncols,
             const float* __restrict__ gamma, const float* __restrict__ beta,
             fp16* __restrict__ hi)
{
    __shared__ float row[768];
    __shared__ float red[8];
    int m = blockIdx.x;
    int tid = threadIdx.x;
    const float* src = in + (size_t)m * ld;

    float lsum = 0.f;
    for (int c = tid; c < ncols; c += 256) { float v = src[c]; row[c] = v; lsum += v; }
#pragma unroll
    for (int o = 16; o; o >>= 1) lsum += __shfl_xor_sync(0xffffffffu, lsum, o);
    if ((tid & 31) == 0) red[tid >> 5] = lsum;
    __syncthreads();
    float tot = 0.f;
#pragma unroll
    for (int i = 0; i < 8; i++) tot += red[i];
    float mu = tot / (float)ncols;
    __syncthreads();

    float lsq = 0.f;
    for (int c = tid; c < ncols; c += 256) { float d = row[c] - mu; lsq += d * d; }
#pragma unroll
    for (int o = 16; o; o >>= 1) lsq += __shfl_xor_sync(0xffffffffu, lsq, o);
    if ((tid & 31) == 0) red[tid >> 5] = lsq;
    __syncthreads();
    float tot2 = 0.f;
#pragma unroll
    for (int i = 0; i < 8; i++) tot2 += red[i];
    float inv = rsqrtf(tot2 / (float)ncols + 1e-5f);

    int nch = ncols >> 3;
    for (int ch = tid; ch < nch; ch += 256) {
        int c0 = ch << 3;
        fp16 h[8];
#pragma unroll
        for (int j = 0; j < 8; j++) {
            int c = c0 + j;
            h[j] = __float2half_rn((row[c] - mu) * inv * gamma[c] + beta[c]);
        }
        *(uint4*)(hi + pidx(m, c0, ncols)) = *(uint4*)h;
    }
}

// ---------------------------------------------------------------------------
// PTX helpers
// ---------------------------------------------------------------------------
__device__ __forceinline__ void ldsm4(unsigned& r0, unsigned& r1, unsigned& r2,
                                      unsigned& r3, unsigned addr) {
    asm volatile("ldmatrix.sync.aligned.m8n8.x4.shared.b16 {%0,%1,%2,%3}, [%4];"
                 : "=r"(r0), "=r"(r1), "=r"(r2), "=r"(r3) : "r"(addr));
}
__device__ __forceinline__ void mma16(float* d, const unsigned* a, const unsigned* b) {
    asm volatile(
        "mma.sync.aligned.m16n8k16.row.col.f32.f16.f16.f32 "
        "{%0,%1,%2,%3},{%4,%5,%6,%7},{%8,%9},{%0,%1,%2,%3};"
        : "+f"(d[0]), "+f"(d[1]), "+f"(d[2]), "+f"(d[3])
        : "r"(a[0]), "r"(a[1]), "r"(a[2]), "r"(a[3]), "r"(b[0]), "r"(b[1]));
}
__device__ __forceinline__ void bulk_ld(unsigned dst, const void* src, unsigned mbar) {
    asm volatile(
        "cp.async.bulk.shared::cluster.global.mbarrier::complete_tx::bytes "
        "[%0], [%1], %2, [%3];"
        :: "r"(dst), "l"(src), "r"(16384u), "r"(mbar) : "memory");
}
__device__ __forceinline__ void mbar_init(unsigned mbar, unsigned cnt) {
    asm volatile("mbarrier.init.shared.b64 [%0], %1;" :: "r"(mbar), "r"(cnt) : "memory");
}
__device__ __forceinline__ void mbar_expect(unsigned mbar, unsigned bytes) {
    asm volatile("mbarrier.arrive.expect_tx.shared.b64 _, [%0], %1;"
                 :: "r"(mbar), "r"(bytes) : "memory");
}
__device__ __forceinline__ void mbar_arrive(unsigned mbar) {
    asm volatile("mbarrier.arrive.shared.b64 _, [%0];" :: "r"(mbar) : "memory");
}
__device__ __forceinline__ void mbar_wait(unsigned mbar, unsigned phase) {
    asm volatile(
        "{\n\t.reg .pred P;\n\t"
        "W%=:\n\t"
        "mbarrier.try_wait.parity.acquire.cta.shared::cta.b64 P, [%0], %1, 0x989680;\n\t"
        "@P bra D%=;\n\t"
        "bra W%=;\n\t"
        "D%=:\n\t}"
        :: "r"(mbar), "r"(phase) : "memory");
}

// ---------------------------------------------------------------------------
// fp16 single-pass GEMM (NT): C = Ahi @ Bhi^T + bias
// CTA tile 128(M) x 256(N), k-block 64, 4-stage 48KB ring (Ah 16K | Bh 32K).
// 544 threads: 16 compute warps (warp tile 32x64) + 1 producer warp.
// EPI 0: plain [M,N] store.  EPI 1: q + RoPE scatter.  EPI 2: kv scatter.
// ---------------------------------------------------------------------------
#define STAGE 49152u
#define NST 4
#define SMEM_TOTAL (NST * 49152 + 64)

template <int EPI>
__global__ __launch_bounds__(544, 1)
void gemm_hmma(const fp16* __restrict__ Ahi, const fp16* __restrict__ Bhi,
               const float* __restrict__ bias, float* __restrict__ out,
               int N, int K,
               const float* __restrict__ ctab, const float* __restrict__ stab)
{
    extern __shared__ __align__(1024) char smem[];
    const unsigned sbase  = (unsigned)__cvta_generic_to_shared(smem);
    const unsigned fullb  = sbase + NST * STAGE;   // NST x 8B
    const unsigned emptyb = fullb + NST * 8;       // NST x 8B

    const int tid  = threadIdx.x;
    const int lane = tid & 31;
    const int wid  = tid >> 5;
    const int m0 = blockIdx.y * 128;
    const int n0 = blockIdx.x * 256;
    const int KB = K >> 6;
    const int ntile0 = n0 >> 7;

    if (tid == 0) {
#pragma unroll
        for (int s = 0; s < NST; s++) {
            mbar_init(fullb + s * 8, 1);
            mbar_init(emptyb + s * 8, 16);
        }
        asm volatile("fence.proxy.async.shared::cta;" ::: "memory");
    }
    __syncthreads();

    if (wid == 16) {
        // ---------------- producer warp ----------------
        if (lane == 0) {
            int eph[NST];
#pragma unroll
            for (int s = 0; s < NST; s++) eph[s] = 0;
            int st = 0;
            for (int kb = 0; kb < KB; kb++) {
                unsigned stg = sbase + st * STAGE;
                unsigned fb = fullb + st * 8;
                if (kb >= NST) { mbar_wait(emptyb + st * 8, eph[st]); eph[st] ^= 1; }
                mbar_expect(fb, STAGE);
                size_t aoff = ((size_t)blockIdx.y * KB + kb) * 8192;
                bulk_ld(stg, Ahi + aoff, fb);
                size_t b0 = ((size_t)ntile0 * KB + kb) * 8192;
                size_t b1 = ((size_t)(ntile0 + 1) * KB + kb) * 8192;
                bulk_ld(stg + 16384, Bhi + b0, fb);
                bulk_ld(stg + 32768, Bhi + b1, fb);
                if (++st == NST) st = 0;
            }
        }
        return;
    }

    // ---------------- compute warps ----------------
    const int wm = wid & 3;       // 0..3 along M (32 rows)
    const int wn = wid >> 2;      // 0..3 along N (64 cols)
    const int r = lane >> 2;
    const int c = lane & 3;

    float acc[2][8][4];
#pragma unroll
    for (int mt = 0; mt < 2; mt++)
#pragma unroll
        for (int nt = 0; nt < 8; nt++)
#pragma unroll
            for (int e = 0; e < 4; e++) acc[mt][nt][e] = 0.f;

    int fph[NST];
#pragma unroll
    for (int s = 0; s < NST; s++) fph[s] = 0;
    int st = 0;
    for (int kb = 0; kb < KB; kb++) {
        mbar_wait(fullb + st * 8, fph[st]);
        fph[st] ^= 1;
        const unsigned stage = sbase + st * STAGE;
#pragma unroll
        for (int t = 0; t < 4; t++) {
            unsigned ah[2][4];
            const int gA = t * 2 + (lane >> 4);
#pragma unroll
            for (int mt = 0; mt < 2; mt++) {
                int rowA = wm * 32 + mt * 16 + (lane & 15);
                unsigned off = stage + rowA * 128 + (((unsigned)(gA ^ (rowA & 7))) << 4);
                ldsm4(ah[mt][0], ah[mt][1], ah[mt][2], ah[mt][3], off);
            }
            const int gB = t * 2 + ((lane >> 3) & 1);
            const int rB = (lane & 7) + ((lane & 16) >> 1);
#pragma unroll
            for (int np = 0; np < 4; np++) {
                int rowB = wn * 64 + np * 16 + rB;
                unsigned off = stage + 16384 + ((rowB >> 7) << 14)
                             + (rowB & 127) * 128 + (((unsigned)(gB ^ (rowB & 7))) << 4);
                unsigned bh[4];
                ldsm4(bh[0], bh[1], bh[2], bh[3], off);
#pragma unroll
                for (int mt = 0; mt < 2; mt++) {
                    mma16(acc[mt][2 * np],     ah[mt], bh);
                    mma16(acc[mt][2 * np + 1], ah[mt], bh + 2);
                }
            }
        }
        if (lane == 0) mbar_arrive(emptyb + st * 8);
        if (++st == NST) st = 0;
    }

    // ---- bias ----
#pragma unroll
    for (int nt = 0; nt < 8; nt++) {
        int nb = n0 + wn * 64 + nt * 8 + 2 * c;
        float b0 = 0.f, b1 = 0.f;
        if (EPI != 0 || nb < N)     b0 = bias[nb];
        if (EPI != 0 || nb + 1 < N) b1 = bias[nb + 1];
#pragma unroll
        for (int mt = 0; mt < 2; mt++) {
            acc[mt][nt][0] += b0; acc[mt][nt][1] += b1;
            acc[mt][nt][2] += b0; acc[mt][nt][3] += b1;
        }
    }

    // ---- epilogue ----
    if (EPI == 0) {
#pragma unroll
        for (int mt = 0; mt < 2; mt++)
#pragma unroll
            for (int half = 0; half < 2; half++) {
                int m = m0 + wm * 32 + mt * 16 + r + half * 8;
#pragma unroll
                for (int nt = 0; nt < 8; nt++) {
                    int n = n0 + wn * 64 + nt * 8 + 2 * c;
                    if (n < N)
                        *(float2*)(out + (size_t)m * N + n) =
                            make_float2(acc[mt][nt][half * 2], acc[mt][nt][half * 2 + 1]);
                }
            }
    } else if (EPI == 1) {
#pragma unroll
        for (int mt = 0; mt < 2; mt++)
#pragma unroll
            for (int half = 0; half < 2; half++) {
                int m = m0 + wm * 32 + mt * 16 + r + half * 8;
                int s = m & (S_LEN - 1);
                int bb = m >> 12;
#pragma unroll
                for (int nt = 0; nt < 8; nt++) {
                    int n_base = n0 + wn * 64 + nt * 8;
                    int h = ((n_base >> 6) * 43) >> 7;          // /192
                    int d0 = n_base - h * 192 + 2 * c;
                    size_t obase = (((size_t)(bb * HEADS + h)) * S_LEN + s) * OUT_D;
                    float v0 = acc[mt][nt][half * 2];
                    float v1 = acc[mt][nt][half * 2 + 1];
                    if (d0 >= 128) {
                        int fi = d0 & 31;
                        float c0 = ctab[s * 32 + fi],     s0 = stab[s * 32 + fi];
                        float c1 = ctab[s * 32 + fi + 1], s1 = stab[s * 32 + fi + 1];
                        float p0 = acc[mt][nt ^ 4][half * 2];
                        float p1 = acc[mt][nt ^ 4][half * 2 + 1];
                        float sg = (d0 & 32) ? 1.f : -1.f;
                        v0 = v0 * c0 + sg * p0 * s0;
                        v1 = v1 * c1 + sg * p1 * s1;
                    }
                    *(float2*)(out + obase + d0) = make_float2(v0, v1);
                }
            }
    } else {
#pragma unroll
        for (int mt = 0; mt < 2; mt++)
#pragma unroll
            for (int half = 0; half < 2; half++) {
                int m = m0 + wm * 32 + mt * 16 + r + half * 8;
                int s = m & (S_LEN - 1);
                int bb = m >> 12;
#pragma unroll
                for (int nt = 0; nt < 8; nt++) {
                    int n_base = n0 + wn * 64 + nt * 8;
                    int h = n_base >> 8;
                    int d = (n_base & 255) + 2 * c;
                    int off = (d < 128) ? (192 + d) : (256 + d);
                    size_t obase = (((size_t)(bb * HEADS + h)) * S_LEN + s) * OUT_D;
                    *(float2*)(out + obase + off) =
                        make_float2(acc[mt][nt][half * 2], acc[mt][nt][half * 2 + 1]);
                }
            }
    }
}

// ---------------------------------------------------------------------------
// k_rot: RoPE on kv_c[:, 512:576] (pre-LN), broadcast to all 16 heads
// ---------------------------------------------------------------------------
__global__ void krot_kernel(const float* __restrict__ kvc,
                            const float* __restrict__ ctab,
                            const float* __restrict__ stab,
                            float* __restrict__ out)
{
    int t = blockIdx.x;
    int d = threadIdx.x;
    int s = t & (S_LEN - 1);
    int bb = t >> 12;
    const float* kr = kvc + (size_t)t * (KV_LR + QK_ROPE) + KV_LR;
    float x = kr[d];
    float p = kr[d ^ 32];
    int fidx = d & 31;
    float cv = ctab[s * 32 + fidx];
    float sv = stab[s * 32 + fidx];
    float res = x * cv + ((d < 32) ? -p : p) * sv;
#pragma unroll
    for (int h = 0; h < HEADS; h++)
        out[(((size_t)bb * HEADS + h) * S_LEN + s) * OUT_D + 320 + d] = res;
}

// ---------------------------------------------------------------------------
extern "C" void kernel_launch(void* const* d_in, const int* in_sizes, int n_in,
                              void* d_out, int out_size)
{
    const float* hidden  = (const float*)d_in[0];
    const float* w_qa    = (const float*)d_in[1];
    const float* b_qa    = (const float*)d_in[2];
    const float* g_qa_ln = (const float*)d_in[3];
    const float* b_qa_ln = (const float*)d_in[4];
    const float* w_qb    = (const float*)d_in[5];
    const float* b_qb    = (const float*)d_in[6];
    const float* w_kva   = (const float*)d_in[7];
    const float* b_kva   = (const float*)d_in[8];
    const float* g_kva_ln= (const float*)d_in[9];
    const float* b_kva_ln= (const float*)d_in[10];
    const float* w_kvb   = (const float*)d_in[11];
    const float* b_kvb   = (const float*)d_in[12];
    float* out = (float*)d_out;

    fp16 *hid_hi, *wqa_hi, *wkva_hi, *wqb_hi, *wkvb_hi, *qln_hi, *kvln_hi;
    float *qc, *kvc, *ct, *st;
    cudaGetSymbolAddress((void**)&hid_hi,  g_hid_hi);
    cudaGetSymbolAddress((void**)&wqa_hi,  g_wqa_hi);
    cudaGetSymbolAddress((void**)&wkva_hi, g_wkva_hi);
    cudaGetSymbolAddress((void**)&wqb_hi,  g_wqb_hi);
    cudaGetSymbolAddress((void**)&wkvb_hi, g_wkvb_hi);
    cudaGetSymbolAddress((void**)&qln_hi,  g_qln_hi);
    cudaGetSymbolAddress((void**)&kvln_hi, g_kvln_hi);
    cudaGetSymbolAddress((void**)&qc,  g_qc);
    cudaGetSymbolAddress((void**)&kvc, g_kvc);
    cudaGetSymbolAddress((void**)&ct,  g_cos);
    cudaGetSymbolAddress((void**)&st,  g_sin);

    static bool attr_set = false;
    if (!attr_set) {
        cudaFuncSetAttribute((const void*)gemm_hmma<0>, cudaFuncAttributeMaxDynamicSharedMemorySize, SMEM_TOTAL);
        cudaFuncSetAttribute((const void*)gemm_hmma<1>, cudaFuncAttributeMaxDynamicSharedMemorySize, SMEM_TOTAL);
        cudaFuncSetAttribute((const void*)gemm_hmma<2>, cudaFuncAttributeMaxDynamicSharedMemorySize, SMEM_TOTAL);
        attr_set = true;
    }

    rope_table_kernel<<<(S_LEN * 32 + 255) / 256, 256>>>(ct, st);

    // pack hidden and weights (hi planes only)
    {
        long long nch;
        nch = (long long)NTOK * (HID >> 3);
        pack1<<<(unsigned)((nch + 255) / 256), 256>>>(hidden, hid_hi, NTOK, NTOK, HID);
        nch = (long long)768 * (HID >> 3);
        pack1<<<(unsigned)((nch + 255) / 256), 256>>>(w_qa,  wqa_hi,  768, 768, HID);
        pack1<<<(unsigned)((nch + 255) / 256), 256>>>(w_kva, wkva_hi, 576, 768, HID);
        nch = (long long)3072 * (Q_LR >> 3);
        pack1<<<(unsigned)((nch + 255) / 256), 256>>>(w_qb,  wqb_hi,  3072, 3072, Q_LR);
        nch = (long long)4096 * (KV_LR >> 3);
        pack1<<<(unsigned)((nch + 255) / 256), 256>>>(w_kvb, wkvb_hi, 4096, 4096, KV_LR);
    }

    // down-projections (single-pass fp16)
    gemm_hmma<0><<<dim3(3, 64), 544, SMEM_TOTAL>>>(hid_hi, wqa_hi,
                                                   b_qa, qc, Q_LR, HID, nullptr, nullptr);
    gemm_hmma<0><<<dim3(3, 64), 544, SMEM_TOTAL>>>(hid_hi, wkva_hi,
                                                   b_kva, kvc, KV_LR + QK_ROPE, HID, nullptr, nullptr);

    // layernorms + pack
    ln_pack<<<NTOK, 256>>>(qc,  Q_LR,            Q_LR,  g_qa_ln,  b_qa_ln,  qln_hi);
    ln_pack<<<NTOK, 256>>>(kvc, KV_LR + QK_ROPE, KV_LR, g_kva_ln, b_kva_ln, kvln_hi);

    // up-projections (single-pass fp16) with fused RoPE / scatter epilogues
    gemm_hmma<1><<<dim3(12, 64), 544, SMEM_TOTAL>>>(qln_hi, wqb_hi,
                                                    b_qb, out, HEADS * QK_HEAD, Q_LR, ct, st);
    gemm_hmma<2><<<dim3(16, 64), 544, SMEM_TOTAL>>>(kvln_hi, wkvb_hi,
                                                    b_kvb, out, HEADS * KV_HEAD, KV_LR, ct, st);

    // k_rot broadcast
    krot_kernel<<<NTOK, 64>>>(kvc, ct, st, out);
}

// round 13
// speedup vs baseline: 7.6081x; 1.2056x over previous
#include <cuda_runtime.h>
#include <cuda_fp16.h>
#include <math.h>
#include <stdint.h>

// Problem constants
#define B_SZ   2
#define S_LEN  4096
#define HID    2048
#define Q_LR   768
#define KV_LR  512
#define QK_ROPE 64
#define QK_NOPE 128
#define HEADS  16
#define QK_HEAD 192
#define KV_HEAD 256
#define NTOK   (B_SZ * S_LEN)   // 8192
#define OUT_D  512

typedef __half fp16;

// ---------------------------------------------------------------------------
// Device scratch. fp16 planes in tiled SW128 layout:
// elem(m,k) -> tile (m>>7, k>>6) [tile = 8192 elems = 128 rows x 128B],
// row r=m&127, 16B chunk g=(k>>3)&7 stored at chunk (g ^ (r&7)).
// Down weights stacked: rows 0..767 = w_qa, rows 768..1343 = w_kva (pad 1536).
// ---------------------------------------------------------------------------
__device__ __align__(1024) fp16 g_hid_hi  [NTOK * HID];
__device__ __align__(1024) fp16 g_wdown_hi[1536 * HID];
__device__ __align__(1024) fp16 g_wqb_hi  [3072 * Q_LR];
__device__ __align__(1024) fp16 g_wkvb_hi [4096 * KV_LR];
__device__ __align__(1024) fp16 g_qln_hi  [NTOK * Q_LR];
__device__ __align__(1024) fp16 g_kvln_hi [NTOK * KV_LR];
__device__ float g_qc [NTOK * Q_LR];
__device__ float g_kvc[NTOK * (KV_LR + QK_ROPE)];
__device__ float g_cos[S_LEN * 32];
__device__ float g_sin[S_LEN * 32];

__device__ __forceinline__ size_t pidx(int m, int k, int K) {
    size_t tile = (size_t)((m >> 7) * (K >> 6) + (k >> 6)) * 8192;
    int r = m & 127;
    int g = (k >> 3) & 7;
    return tile + r * 64 + ((g ^ (r & 7)) << 3) + (k & 7);
}

// ---------------------------------------------------------------------------
__global__ void rope_table_kernel(float* __restrict__ ct, float* __restrict__ st) {
    int idx = blockIdx.x * blockDim.x + threadIdx.x;
    if (idx >= S_LEN * 32) return;
    int s = idx >> 5;
    int f = idx & 31;
    double inv = exp(-(double)f * (log(10000.0) / 32.0));
    double fr = (double)s * inv;
    ct[idx] = (float)cos(fr);
    st[idx] = (float)sin(fr);
}

// ---------------------------------------------------------------------------
// Pack fp32 [M,K] -> hi fp16 tiled plane at row offset moff (moff % 128 == 0)
// ---------------------------------------------------------------------------
__global__ void pack1(const float* __restrict__ src, fp16* __restrict__ hi,
                      int M, int Mpad, int K, int moff)
{
    long long c = (long long)blockIdx.x * blockDim.x + threadIdx.x;
    long long nch = (long long)Mpad * (K >> 3);
    if (c >= nch) return;
    int kc = (int)(c % (K >> 3));
    int m  = (int)(c / (K >> 3));
    int k0 = kc << 3;
    fp16 h[8];
#pragma unroll
    for (int j = 0; j < 8; j++) {
        float v = (m < M) ? src[(size_t)m * K + k0 + j] : 0.f;
        h[j] = __float2half_rn(v);
    }
    *(uint4*)(hi + pidx(m + moff, k0, K)) = *(uint4*)h;
}

// ---------------------------------------------------------------------------
// LayerNorm + pack into fp16 hi plane (row-per-block)
// ---------------------------------------------------------------------------
__global__ __launch_bounds__(256)
void ln_pack(const float* __restrict__ in, int ld, int ncols,
             const float* __restrict__ gamma, const float* __restrict__ beta,
             fp16* __restrict__ hi)
{
    __shared__ float row[768];
    __shared__ float red[8];
    int m = blockIdx.x;
    int tid = threadIdx.x;
    const float* src = in + (size_t)m * ld;

    float lsum = 0.f;
    for (int c = tid; c < ncols; c += 256) { float v = src[c]; row[c] = v; lsum += v; }
#pragma unroll
    for (int o = 16; o; o >>= 1) lsum += __shfl_xor_sync(0xffffffffu, lsum, o);
    if ((tid & 31) == 0) red[tid >> 5] = lsum;
    __syncthreads();
    float tot = 0.f;
#pragma unroll
    for (int i = 0; i < 8; i++) tot += red[i];
    float mu = tot / (float)ncols;
    __syncthreads();

    float lsq = 0.f;
    for (int c = tid; c < ncols; c += 256) { float d = row[c] - mu; lsq += d * d; }
#pragma unroll
    for (int o = 16; o; o >>= 1) lsq += __shfl_xor_sync(0xffffffffu, lsq, o);
    if ((tid & 31) == 0) red[tid >> 5] = lsq;
    __syncthreads();
    float tot2 = 0.f;
#pragma unroll
    for (int i = 0; i < 8; i++) tot2 += red[i];
    float inv = rsqrtf(tot2 / (float)ncols + 1e-5f);

    int nch = ncols >> 3;
    for (int ch = tid; ch < nch; ch += 256) {
        int c0 = ch << 3;
        fp16 h[8];
#pragma unroll
        for (int j = 0; j < 8; j++) {
            int c = c0 + j;
            h[j] = __float2half_rn((row[c] - mu) * inv * gamma[c] + beta[c]);
        }
        *(uint4*)(hi + pidx(m, c0, ncols)) = *(uint4*)h;
    }
}

// ---------------------------------------------------------------------------
// PTX helpers
// ---------------------------------------------------------------------------
__device__ __forceinline__ void ldsm4(unsigned& r0, unsigned& r1, unsigned& r2,
                                      unsigned& r3, unsigned addr) {
    asm volatile("ldmatrix.sync.aligned.m8n8.x4.shared.b16 {%0,%1,%2,%3}, [%4];"
                 : "=r"(r0), "=r"(r1), "=r"(r2), "=r"(r3) : "r"(addr));
}
__device__ __forceinline__ void mma16(float* d, const unsigned* a, const unsigned* b) {
    asm volatile(
        "mma.sync.aligned.m16n8k16.row.col.f32.f16.f16.f32 "
        "{%0,%1,%2,%3},{%4,%5,%6,%7},{%8,%9},{%0,%1,%2,%3};"
        : "+f"(d[0]), "+f"(d[1]), "+f"(d[2]), "+f"(d[3])
        : "r"(a[0]), "r"(a[1]), "r"(a[2]), "r"(a[3]), "r"(b[0]), "r"(b[1]));
}
__device__ __forceinline__ void bulk_ld(unsigned dst, const void* src, unsigned mbar) {
    asm volatile(
        "cp.async.bulk.shared::cluster.global.mbarrier::complete_tx::bytes "
        "[%0], [%1], %2, [%3];"
        :: "r"(dst), "l"(src), "r"(16384u), "r"(mbar) : "memory");
}
__device__ __forceinline__ void mbar_init(unsigned mbar, unsigned cnt) {
    asm volatile("mbarrier.init.shared.b64 [%0], %1;" :: "r"(mbar), "r"(cnt) : "memory");
}
__device__ __forceinline__ void mbar_expect(unsigned mbar, unsigned bytes) {
    asm volatile("mbarrier.arrive.expect_tx.shared.b64 _, [%0], %1;"
                 :: "r"(mbar), "r"(bytes) : "memory");
}
__device__ __forceinline__ void mbar_arrive(unsigned mbar) {
    asm volatile("mbarrier.arrive.shared.b64 _, [%0];" :: "r"(mbar) : "memory");
}
__device__ __forceinline__ void mbar_wait(unsigned mbar, unsigned phase) {
    asm volatile(
        "{\n\t.reg .pred P;\n\t"
        "W%=:\n\t"
        "mbarrier.try_wait.parity.acquire.cta.shared::cta.b64 P, [%0], %1, 0x989680;\n\t"
        "@P bra D%=;\n\t"
        "bra W%=;\n\t"
        "D%=:\n\t}"
        :: "r"(mbar), "r"(phase) : "memory");
}

// ---------------------------------------------------------------------------
// fp16 single-pass GEMM (NT): C = Ahi @ Bhi^T + bias
// CTA tile 128(M) x 256(N), k-block 64, 4-stage 48KB ring (Ah 16K | Bh 32K).
// 544 threads: 16 compute warps (warp tile 32x64) + 1 producer warp.
// EPI 3: fused down-proj -> split store qc (n<768) / kvc (768<=n<1344)
// EPI 1: q up-proj + RoPE scatter.   EPI 2: kv up-proj scatter.
// ---------------------------------------------------------------------------
#define STAGE 49152u
#define NST 4
#define SMEM_TOTAL (NST * 49152 + 64)

template <int EPI>
__global__ __launch_bounds__(544, 1)
void gemm_hmma(const fp16* __restrict__ Ahi, const fp16* __restrict__ Bhi,
               const float* __restrict__ bias, float* __restrict__ out,
               int N, int K,
               const float* __restrict__ ctab, const float* __restrict__ stab,
               const float* __restrict__ bias2, float* __restrict__ out2)
{
    extern __shared__ __align__(1024) char smem[];
    const unsigned sbase  = (unsigned)__cvta_generic_to_shared(smem);
    const unsigned fullb  = sbase + NST * STAGE;   // NST x 8B
    const unsigned emptyb = fullb + NST * 8;       // NST x 8B

    const int tid  = threadIdx.x;
    const int lane = tid & 31;
    const int wid  = tid >> 5;
    const int m0 = blockIdx.y * 128;
    const int n0 = blockIdx.x * 256;
    const int KB = K >> 6;
    const int ntile0 = n0 >> 7;

    if (tid == 0) {
#pragma unroll
        for (int s = 0; s < NST; s++) {
            mbar_init(fullb + s * 8, 1);
            mbar_init(emptyb + s * 8, 16);
        }
        asm volatile("fence.proxy.async.shared::cta;" ::: "memory");
    }
    __syncthreads();

    if (wid == 16) {
        // ---------------- producer warp ----------------
        if (lane == 0) {
            int eph[NST];
#pragma unroll
            for (int s = 0; s < NST; s++) eph[s] = 0;
            int st = 0;
            for (int kb = 0; kb < KB; kb++) {
                unsigned stg = sbase + st * STAGE;
                unsigned fb = fullb + st * 8;
                if (kb >= NST) { mbar_wait(emptyb + st * 8, eph[st]); eph[st] ^= 1; }
                mbar_expect(fb, STAGE);
                size_t aoff = ((size_t)blockIdx.y * KB + kb) * 8192;
                bulk_ld(stg, Ahi + aoff, fb);
                size_t b0 = ((size_t)ntile0 * KB + kb) * 8192;
                size_t b1 = ((size_t)(ntile0 + 1) * KB + kb) * 8192;
                bulk_ld(stg + 16384, Bhi + b0, fb);
                bulk_ld(stg + 32768, Bhi + b1, fb);
                if (++st == NST) st = 0;
            }
        }
        return;
    }

    // ---------------- compute warps ----------------
    const int wm = wid & 3;       // 0..3 along M (32 rows)
    const int wn = wid >> 2;      // 0..3 along N (64 cols)
    const int r = lane >> 2;
    const int c = lane & 3;

    float acc[2][8][4];
#pragma unroll
    for (int mt = 0; mt < 2; mt++)
#pragma unroll
        for (int nt = 0; nt < 8; nt++)
#pragma unroll
            for (int e = 0; e < 4; e++) acc[mt][nt][e] = 0.f;

    int fph[NST];
#pragma unroll
    for (int s = 0; s < NST; s++) fph[s] = 0;
    int st = 0;
    for (int kb = 0; kb < KB; kb++) {
        mbar_wait(fullb + st * 8, fph[st]);
        fph[st] ^= 1;
        const unsigned stage = sbase + st * STAGE;
#pragma unroll
        for (int t = 0; t < 4; t++) {
            unsigned ah[2][4];
            const int gA = t * 2 + (lane >> 4);
#pragma unroll
            for (int mt = 0; mt < 2; mt++) {
                int rowA = wm * 32 + mt * 16 + (lane & 15);
                unsigned off = stage + rowA * 128 + (((unsigned)(gA ^ (rowA & 7))) << 4);
                ldsm4(ah[mt][0], ah[mt][1], ah[mt][2], ah[mt][3], off);
            }
            const int gB = t * 2 + ((lane >> 3) & 1);
            const int rB = (lane & 7) + ((lane & 16) >> 1);
#pragma unroll
            for (int np = 0; np < 4; np++) {
                int rowB = wn * 64 + np * 16 + rB;
                unsigned off = stage + 16384 + ((rowB >> 7) << 14)
                             + (rowB & 127) * 128 + (((unsigned)(gB ^ (rowB & 7))) << 4);
                unsigned bh[4];
                ldsm4(bh[0], bh[1], bh[2], bh[3], off);
#pragma unroll
                for (int mt = 0; mt < 2; mt++) {
                    mma16(acc[mt][2 * np],     ah[mt], bh);
                    mma16(acc[mt][2 * np + 1], ah[mt], bh + 2);
                }
            }
        }
        if (lane == 0) mbar_arrive(emptyb + st * 8);
        if (++st == NST) st = 0;
    }

    // ---- bias (EPI 1/2: direct; EPI 3 handles bias inline) ----
    if (EPI != 3) {
#pragma unroll
        for (int nt = 0; nt < 8; nt++) {
            int nb = n0 + wn * 64 + nt * 8 + 2 * c;
            float b0 = bias[nb];
            float b1 = bias[nb + 1];
#pragma unroll
            for (int mt = 0; mt < 2; mt++) {
                acc[mt][nt][0] += b0; acc[mt][nt][1] += b1;
                acc[mt][nt][2] += b0; acc[mt][nt][3] += b1;
            }
        }
    }

    // ---- epilogue ----
    if (EPI == 3) {
        // fused down-proj split: n<768 -> qc[m,768], 768<=n<1344 -> kvc[m,576]
        const int nwb = n0 + wn * 64;          // 64-aligned, uniform per warp
        if (nwb < 1344) {
            const bool isq = (nwb < 768);
            float* dst0 = isq ? out : out2;
            const float* bsrc = isq ? bias : bias2;
            const int ldd = isq ? 768 : 576;
            const int ncol = isq ? nwb : (nwb - 768);
#pragma unroll
            for (int mt = 0; mt < 2; mt++)
#pragma unroll
                for (int half = 0; half < 2; half++) {
                    int m = m0 + wm * 32 + mt * 16 + r + half * 8;
#pragma unroll
                    for (int nt = 0; nt < 8; nt++) {
                        int nn = ncol + nt * 8 + 2 * c;
                        float v0 = acc[mt][nt][half * 2]     + bsrc[nn];
                        float v1 = acc[mt][nt][half * 2 + 1] + bsrc[nn + 1];
                        *(float2*)(dst0 + (size_t)m * ldd + nn) = make_float2(v0, v1);
                    }
                }
        }
    } else if (EPI == 1) {
#pragma unroll
        for (int mt = 0; mt < 2; mt++)
#pragma unroll
            for (int half = 0; half < 2; half++) {
                int m = m0 + wm * 32 + mt * 16 + r + half * 8;
                int s = m & (S_LEN - 1);
                int bb = m >> 12;
#pragma unroll
                for (int nt = 0; nt < 8; nt++) {
                    int n_base = n0 + wn * 64 + nt * 8;
                    int h = ((n_base >> 6) * 43) >> 7;          // /192
                    int d0 = n_base - h * 192 + 2 * c;
                    size_t obase = (((size_t)(bb * HEADS + h)) * S_LEN + s) * OUT_D;
                    float v0 = acc[mt][nt][half * 2];
                    float v1 = acc[mt][nt][half * 2 + 1];
                    if (d0 >= 128) {
                        int fi = d0 & 31;
                        float c0 = ctab[s * 32 + fi],     s0 = stab[s * 32 + fi];
                        float c1 = ctab[s * 32 + fi + 1], s1 = stab[s * 32 + fi + 1];
                        float p0 = acc[mt][nt ^ 4][half * 2];
                        float p1 = acc[mt][nt ^ 4][half * 2 + 1];
                        float sg = (d0 & 32) ? 1.f : -1.f;
                        v0 = v0 * c0 + sg * p0 * s0;
                        v1 = v1 * c1 + sg * p1 * s1;
                    }
                    *(float2*)(out + obase + d0) = make_float2(v0, v1);
                }
            }
    } else {
#pragma unroll
        for (int mt = 0; mt < 2; mt++)
#pragma unroll
            for (int half = 0; half < 2; half++) {
                int m = m0 + wm * 32 + mt * 16 + r + half * 8;
                int s = m & (S_LEN - 1);
                int bb = m >> 12;
#pragma unroll
                for (int nt = 0; nt < 8; nt++) {
                    int n_base = n0 + wn * 64 + nt * 8;
                    int h = n_base >> 8;
                    int d = (n_base & 255) + 2 * c;
                    int off = (d < 128) ? (192 + d) : (256 + d);
                    size_t obase = (((size_t)(bb * HEADS + h)) * S_LEN + s) * OUT_D;
                    *(float2*)(out + obase + off) =
                        make_float2(acc[mt][nt][half * 2], acc[mt][nt][half * 2 + 1]);
                }
            }
    }
}

// ---------------------------------------------------------------------------
// k_rot: RoPE on kv_c[:, 512:576] (pre-LN), broadcast to all 16 heads
// ---------------------------------------------------------------------------
__global__ void krot_kernel(const float* __restrict__ kvc,
                            const float* __restrict__ ctab,
                            const float* __restrict__ stab,
                            float* __restrict__ out)
{
    int t = blockIdx.x;
    int d = threadIdx.x;
    int s = t & (S_LEN - 1);
    int bb = t >> 12;
    const float* kr = kvc + (size_t)t * (KV_LR + QK_ROPE) + KV_LR;
    float x = kr[d];
    float p = kr[d ^ 32];
    int fidx = d & 31;
    float cv = ctab[s * 32 + fidx];
    float sv = stab[s * 32 + fidx];
    float res = x * cv + ((d < 32) ? -p : p) * sv;
#pragma unroll
    for (int h = 0; h < HEADS; h++)
        out[(((size_t)bb * HEADS + h) * S_LEN + s) * OUT_D + 320 + d] = res;
}

// ---------------------------------------------------------------------------
extern "C" void kernel_launch(void* const* d_in, const int* in_sizes, int n_in,
                              void* d_out, int out_size)
{
    const float* hidden  = (const float*)d_in[0];
    const float* w_qa    = (const float*)d_in[1];
    const float* b_qa    = (const float*)d_in[2];
    const float* g_qa_ln = (const float*)d_in[3];
    const float* b_qa_ln = (const float*)d_in[4];
    const float* w_qb    = (const float*)d_in[5];
    const float* b_qb    = (const float*)d_in[6];
    const float* w_kva   = (const float*)d_in[7];
    const float* b_kva   = (const float*)d_in[8];
    const float* g_kva_ln= (const float*)d_in[9];
    const float* b_kva_ln= (const float*)d_in[10];
    const float* w_kvb   = (const float*)d_in[11];
    const float* b_kvb   = (const float*)d_in[12];
    float* out = (float*)d_out;

    fp16 *hid_hi, *wdown_hi, *wqb_hi, *wkvb_hi, *qln_hi, *kvln_hi;
    float *qc, *kvc, *ct, *st;
    cudaGetSymbolAddress((void**)&hid_hi,   g_hid_hi);
    cudaGetSymbolAddress((void**)&wdown_hi, g_wdown_hi);
    cudaGetSymbolAddress((void**)&wqb_hi,   g_wqb_hi);
    cudaGetSymbolAddress((void**)&wkvb_hi,  g_wkvb_hi);
    cudaGetSymbolAddress((void**)&qln_hi,   g_qln_hi);
    cudaGetSymbolAddress((void**)&kvln_hi,  g_kvln_hi);
    cudaGetSymbolAddress((void**)&qc,  g_qc);
    cudaGetSymbolAddress((void**)&kvc, g_kvc);
    cudaGetSymbolAddress((void**)&ct,  g_cos);
    cudaGetSymbolAddress((void**)&st,  g_sin);

    static cudaStream_t s1 = nullptr, s2 = nullptr;
    static cudaEvent_t evA, evB, ev1, ev2, evK;
    if (!s1) {
        cudaStreamCreateWithFlags(&s1, cudaStreamNonBlocking);
        cudaStreamCreateWithFlags(&s2, cudaStreamNonBlocking);
        cudaEventCreateWithFlags(&evA, cudaEventDisableTiming);
        cudaEventCreateWithFlags(&evB, cudaEventDisableTiming);
        cudaEventCreateWithFlags(&ev1, cudaEventDisableTiming);
        cudaEventCreateWithFlags(&ev2, cudaEventDisableTiming);
        cudaEventCreateWithFlags(&evK, cudaEventDisableTiming);
        cudaFuncSetAttribute((const void*)gemm_hmma<3>, cudaFuncAttributeMaxDynamicSharedMemorySize, SMEM_TOTAL);
        cudaFuncSetAttribute((const void*)gemm_hmma<1>, cudaFuncAttributeMaxDynamicSharedMemorySize, SMEM_TOTAL);
        cudaFuncSetAttribute((const void*)gemm_hmma<2>, cudaFuncAttributeMaxDynamicSharedMemorySize, SMEM_TOTAL);
    }

    // ---- fork s1: up-projection weight packs + rope table (indep of down path)
    cudaEventRecord(evA, 0);
    cudaStreamWaitEvent(s1, evA, 0);
    {
        long long nch = (long long)3072 * (Q_LR >> 3);
        pack1<<<(unsigned)((nch + 255) / 256), 256, 0, s1>>>(w_qb, wqb_hi, 3072, 3072, Q_LR, 0);
        nch = (long long)4096 * (KV_LR >> 3);
        pack1<<<(unsigned)((nch + 255) / 256), 256, 0, s1>>>(w_kvb, wkvb_hi, 4096, 4096, KV_LR, 0);
        rope_table_kernel<<<(S_LEN * 32 + 255) / 256, 256, 0, s1>>>(ct, st);
    }
    cudaEventRecord(evB, s1);

    // ---- stream 0: down path packs + fused down GEMM
    {
        long long nch = (long long)NTOK * (HID >> 3);
        pack1<<<(unsigned)((nch + 255) / 256), 256>>>(hidden, hid_hi, NTOK, NTOK, HID, 0);
        nch = (long long)768 * (HID >> 3);
        pack1<<<(unsigned)((nch + 255) / 256), 256>>>(w_qa,  wdown_hi, 768, 768, HID, 0);
        pack1<<<(unsigned)((nch + 255) / 256), 256>>>(w_kva, wdown_hi, 576, 768, HID, 768);
    }
    gemm_hmma<3><<<dim3(6, 64), 544, SMEM_TOTAL>>>(hid_hi, wdown_hi,
                                                   b_qa, qc, 1536, HID,
                                                   nullptr, nullptr, b_kva, kvc);
    cudaEventRecord(ev1, 0);

    // ---- stream 0: ln q; s2: ln kv; s1: krot (needs kvc + rope table)
    ln_pack<<<NTOK, 256>>>(qc, Q_LR, Q_LR, g_qa_ln, b_qa_ln, qln_hi);
    cudaStreamWaitEvent(s2, ev1, 0);
    ln_pack<<<NTOK, 256, 0, s2>>>(kvc, KV_LR + QK_ROPE, KV_LR, g_kva_ln, b_kva_ln, kvln_hi);
    cudaStreamWaitEvent(s1, ev1, 0);
    krot_kernel<<<NTOK, 64, 0, s1>>>(kvc, ct, st, out);
    cudaEventRecord(evK, s1);

    // ---- up-projections, concurrent: q on stream 0, kv on s2
    cudaStreamWaitEvent(0, evB, 0);
    gemm_hmma<1><<<dim3(12, 64), 544, SMEM_TOTAL>>>(qln_hi, wqb_hi,
                                                    b_qb, out, HEADS * QK_HEAD, Q_LR,
                                                    ct, st, nullptr, nullptr);
    cudaStreamWaitEvent(s2, evB, 0);
    gemm_hmma<2><<<dim3(16, 64), 544, SMEM_TOTAL, s2>>>(kvln_hi, wkvb_hi,
                                                        b_kvb, out, HEADS * KV_HEAD, KV_LR,
                                                        nullptr, nullptr, nullptr, nullptr);
    cudaEventRecord(ev2, s2);

    // ---- join side streams back into stream 0
    cudaStreamWaitEvent(0, ev2, 0);
    cudaStreamWaitEvent(0, evK, 0);
}